// round 2
// baseline (speedup 1.0000x reference)
#include <cuda_runtime.h>
#include <math.h>

// Problem constants
#define N_TOK 16384      // B*S = 32*512
#define HDIM  2048
#define FPCNT 1024
#define SPCNT 1024
#define CCOLS 2050       // 2 + FP + SP

// Scratch (device globals: allocation-free kernel_launch)
__device__ float g_end_prob[N_TOK];
__device__ int   g_rows[2][N_TOK];
__device__ int   g_cnt[2];
__device__ float g_logits[(size_t)N_TOK * 1024];

__global__ void k_init() {
    g_cnt[0] = 0;
    g_cnt[1] = 0;
}

// One warp per token: end-head GEMV + sigmoid, zero-fill the output segments
// that the GEMM epilogue will NOT write, write class-0 rows fully, and build
// compacted row lists for classes 1/2.
__global__ void k_classify(const float* __restrict__ X,
                           const int* __restrict__ pY,
                           const float* __restrict__ W_end,
                           const float* __restrict__ b_end,
                           float* __restrict__ out) {
    int warp = threadIdx.x >> 5;
    int lane = threadIdx.x & 31;
    int n = blockIdx.x * 8 + warp;
    if (n >= N_TOK) return;

    const float4* x4 = (const float4*)(X + (size_t)n * HDIM);
    const float4* w4 = (const float4*)W_end;
    float s = 0.f;
    #pragma unroll 4
    for (int i = lane; i < HDIM / 4; i += 32) {
        float4 a = x4[i];
        float4 b = w4[i];
        s += a.x * b.x + a.y * b.y + a.z * b.z + a.w * b.w;
    }
    #pragma unroll
    for (int o = 16; o; o >>= 1) s += __shfl_xor_sync(0xffffffffu, s, o);

    float logit = s + b_end[0];
    float ep = 1.f / (1.f + expf(-logit));   // identical on all lanes

    int cls = pY[n];
    float* orow = out + N_TOK + (size_t)n * CCOLS;

    if (cls == 0) {
        for (int j = lane; j < CCOLS; j += 32)
            orow[j] = (j < 2) ? ep : 0.f;
        if (lane == 0) {
            g_end_prob[n] = ep;
            out[n] = logf(ep);
        }
    } else if (cls == 1) {
        for (int j = lane; j < CCOLS; j += 32)
            if (j < 2 || j >= 2 + FPCNT) orow[j] = 0.f;
        if (lane == 0) {
            g_end_prob[n] = ep;
            int r = atomicAdd(&g_cnt[0], 1);
            g_rows[0][r] = n;
        }
    } else {
        for (int j = lane; j < 2 + FPCNT; j += 32)
            orow[j] = 0.f;
        if (lane == 0) {
            g_end_prob[n] = ep;
            int r = atomicAdd(&g_cnt[1], 1);
            g_rows[1][r] = n;
        }
    }
}

// Tiled SGEMM over compacted rows: logits[row, j] = X[row] . W[j] + bias[j]
// 128x128 tile, K-step 16, 256 threads, 8x8 micro-tile per thread.
// Fixed worst-case grid; early-exit on device-side count (graph-capturable).
__global__ __launch_bounds__(256) void k_gemm(
    const float* __restrict__ X,
    const float* __restrict__ W_hcw, const float* __restrict__ b_hcw,
    const float* __restrict__ W_roo, const float* __restrict__ b_roo) {

    int cls = blockIdx.z;
    int cnt = g_cnt[cls];
    int m0 = blockIdx.x * 128;
    if (m0 >= cnt) return;

    const int* rows = g_rows[cls];
    const float* W    = cls ? W_roo : W_hcw;
    const float* bias = cls ? b_roo : b_hcw;
    int n0 = blockIdx.y * 128;

    __shared__ float As[16][128];
    __shared__ float Bs[16][128];

    int tid = threadIdx.x;
    int tm = tid >> 4;      // 0..15 -> rows tm*8..tm*8+7
    int tn = tid & 15;      // 0..15 -> cols tn*8..tn*8+7

    // Each thread loads 2 float4 of A and 2 float4 of B per K-step.
    int aIdx0 = tid, aIdx1 = tid + 256;
    int ai0 = aIdx0 >> 2, ak0 = (aIdx0 & 3) * 4;
    int ai1 = aIdx1 >> 2, ak1 = (aIdx1 & 3) * 4;

    int r0 = rows[min(m0 + ai0, cnt - 1)];
    int r1 = rows[min(m0 + ai1, cnt - 1)];
    const float* arow0 = X + (size_t)r0 * HDIM;
    const float* arow1 = X + (size_t)r1 * HDIM;
    const float* brow0 = W + (size_t)(n0 + ai0) * HDIM;
    const float* brow1 = W + (size_t)(n0 + ai1) * HDIM;

    float acc[8][8];
    #pragma unroll
    for (int x = 0; x < 8; x++)
        #pragma unroll
        for (int y = 0; y < 8; y++) acc[x][y] = 0.f;

    for (int k0 = 0; k0 < HDIM; k0 += 16) {
        float4 a0 = *(const float4*)(arow0 + k0 + ak0);
        float4 a1 = *(const float4*)(arow1 + k0 + ak1);
        float4 b0 = *(const float4*)(brow0 + k0 + ak0);
        float4 b1 = *(const float4*)(brow1 + k0 + ak1);

        __syncthreads();   // previous iteration's reads done
        As[ak0 + 0][ai0] = a0.x; As[ak0 + 1][ai0] = a0.y;
        As[ak0 + 2][ai0] = a0.z; As[ak0 + 3][ai0] = a0.w;
        As[ak1 + 0][ai1] = a1.x; As[ak1 + 1][ai1] = a1.y;
        As[ak1 + 2][ai1] = a1.z; As[ak1 + 3][ai1] = a1.w;
        Bs[ak0 + 0][ai0] = b0.x; Bs[ak0 + 1][ai0] = b0.y;
        Bs[ak0 + 2][ai0] = b0.z; Bs[ak0 + 3][ai0] = b0.w;
        Bs[ak1 + 0][ai1] = b1.x; Bs[ak1 + 1][ai1] = b1.y;
        Bs[ak1 + 2][ai1] = b1.z; Bs[ak1 + 3][ai1] = b1.w;
        __syncthreads();

        #pragma unroll
        for (int k = 0; k < 16; k++) {
            float a[8], b[8];
            #pragma unroll
            for (int x = 0; x < 8; x++) a[x] = As[k][tm * 8 + x];
            #pragma unroll
            for (int y = 0; y < 8; y++) b[y] = Bs[k][tn * 8 + y];
            #pragma unroll
            for (int x = 0; x < 8; x++)
                #pragma unroll
                for (int y = 0; y < 8; y++)
                    acc[x][y] += a[x] * b[y];
        }
    }

    #pragma unroll
    for (int x = 0; x < 8; x++) {
        int mi = m0 + tm * 8 + x;
        if (mi < cnt) {
            int row = rows[mi];
            float* dst = g_logits + (size_t)row * 1024 + n0 + tn * 8;
            #pragma unroll
            for (int y = 0; y < 8; y++)
                dst[y] = acc[x][y] + bias[n0 + tn * 8 + y];
        }
    }
}

// One CTA per compacted row: softmax over 1024 logits, scale by (1-end_prob),
// scatter into the active output segment, gather log-prob at Y.
__global__ __launch_bounds__(256) void k_softmax(const int* __restrict__ Y,
                                                 float* __restrict__ out) {
    int cls = blockIdx.y;
    int cnt = g_cnt[cls];
    int r = blockIdx.x;
    if (r >= cnt) return;
    int n = g_rows[cls][r];

    const float4* L = (const float4*)(g_logits + (size_t)n * 1024);
    int tid = threadIdx.x;            // 256 threads, 4 logits each
    float4 lv = L[tid];

    __shared__ float red[256];
    float m = fmaxf(fmaxf(lv.x, lv.y), fmaxf(lv.z, lv.w));
    red[tid] = m;
    __syncthreads();
    #pragma unroll
    for (int s = 128; s; s >>= 1) {
        if (tid < s) red[tid] = fmaxf(red[tid], red[tid + s]);
        __syncthreads();
    }
    float mx = red[0];
    __syncthreads();

    float e0 = expf(lv.x - mx), e1 = expf(lv.y - mx);
    float e2 = expf(lv.z - mx), e3 = expf(lv.w - mx);
    red[tid] = e0 + e1 + e2 + e3;
    __syncthreads();
    #pragma unroll
    for (int s = 128; s; s >>= 1) {
        if (tid < s) red[tid] += red[tid + s];
        __syncthreads();
    }
    float inv = 1.f / red[0];
    float ne = 1.f - g_end_prob[n];
    float sc = inv * ne;

    float p0 = e0 * sc, p1 = e1 * sc, p2 = e2 * sc, p3 = e3 * sc;
    float* dst = out + N_TOK + (size_t)n * CCOLS + (cls ? (2 + FPCNT) : 2);
    int j = tid * 4;
    dst[j + 0] = p0; dst[j + 1] = p1; dst[j + 2] = p2; dst[j + 3] = p3;

    int yv = Y[n];
    int idx = cls ? (yv - 2 - FPCNT) : (yv - 2);
    idx = max(0, min(idx, 1023));
    if (idx >= j && idx < j + 4) {
        float p = (idx == j) ? p0 : (idx == j + 1) ? p1 : (idx == j + 2) ? p2 : p3;
        out[n] = logf(p);
    }
}

extern "C" void kernel_launch(void* const* d_in, const int* in_sizes, int n_in,
                              void* d_out, int out_size) {
    const float* X     = (const float*)d_in[0];
    const int*   pY    = (const int*)d_in[1];
    const int*   Y     = (const int*)d_in[2];
    const float* W_end = (const float*)d_in[3];
    const float* b_end = (const float*)d_in[4];
    const float* W_hcw = (const float*)d_in[5];
    const float* b_hcw = (const float*)d_in[6];
    const float* W_roo = (const float*)d_in[7];
    const float* b_roo = (const float*)d_in[8];
    float* out = (float*)d_out;

    k_init<<<1, 1>>>();
    k_classify<<<N_TOK / 8, 256>>>(X, pY, W_end, b_end, out);
    k_gemm<<<dim3(N_TOK / 128, 1024 / 128, 2), 256>>>(X, W_hcw, b_hcw, W_roo, b_roo);
    k_softmax<<<dim3(N_TOK, 2), 256>>>(Y, out);
}

// round 7
// speedup vs baseline: 2.0777x; 2.0777x over previous
#include <cuda_runtime.h>
#include <cuda_bf16.h>
#include <math.h>
#include <cstdint>

// Problem constants
#define N_TOK 16384      // B*S = 32*512
#define HDIM  2048
#define FPCNT 1024
#define SPCNT 1024
#define CCOLS 2050       // 2 + FP + SP

// ---------------- device scratch (allocation-free) ----------------
__device__ float g_end_prob[N_TOK];
__device__ int   g_rows[2][N_TOK];
__device__ int   g_cnt[2];
__device__ float g_logits[(size_t)N_TOK * 1024];
__device__ __align__(16) __nv_bfloat16 g_xhi[(size_t)N_TOK * HDIM];
__device__ __align__(16) __nv_bfloat16 g_xlo[(size_t)N_TOK * HDIM];
__device__ __align__(16) __nv_bfloat16 g_whi[(size_t)2 * 1024 * HDIM];
__device__ __align__(16) __nv_bfloat16 g_wlo[(size_t)2 * 1024 * HDIM];

// ---------------- helpers ----------------
__device__ __forceinline__ uint32_t smem_to_u32(const void* p) {
    uint32_t a;
    asm("{ .reg .u64 t; cvta.to.shared.u64 t, %1; cvt.u32.u64 %0, t; }" : "=r"(a) : "l"(p));
    return a;
}

__device__ __forceinline__ void ldsm4(uint32_t* r, uint32_t addr) {
    asm volatile("ldmatrix.sync.aligned.m8n8.x4.shared.b16 {%0,%1,%2,%3}, [%4];"
                 : "=r"(r[0]), "=r"(r[1]), "=r"(r[2]), "=r"(r[3]) : "r"(addr));
}

__device__ __forceinline__ void mma16816(float* c, const uint32_t* a, const uint32_t* b) {
    asm volatile(
        "mma.sync.aligned.m16n8k16.row.col.f32.bf16.bf16.f32 "
        "{%0,%1,%2,%3}, {%4,%5,%6,%7}, {%8,%9}, {%0,%1,%2,%3};"
        : "+f"(c[0]), "+f"(c[1]), "+f"(c[2]), "+f"(c[3])
        : "r"(a[0]), "r"(a[1]), "r"(a[2]), "r"(a[3]), "r"(b[0]), "r"(b[1]));
}

#define CP_ASYNC16(sa, ga) \
    asm volatile("cp.async.cg.shared.global [%0], [%1], 16;" :: "r"(sa), "l"(ga))
#define CP_COMMIT()  asm volatile("cp.async.commit_group;" ::: "memory")
#define CP_WAIT(n)   asm volatile("cp.async.wait_group %0;" :: "n"(n) : "memory")

// ---------------- kernels ----------------
__global__ void k_init() { g_cnt[0] = 0; g_cnt[1] = 0; }

// One warp per token: end-head GEMV + sigmoid, zero-fill inactive output
// segments, compact rows per class, AND emit bf16 hi/lo split of X.
__global__ void k_classify(const float* __restrict__ X,
                           const int* __restrict__ pY,
                           const float* __restrict__ W_end,
                           const float* __restrict__ b_end,
                           float* __restrict__ out) {
    int warp = threadIdx.x >> 5;
    int lane = threadIdx.x & 31;
    int n = blockIdx.x * 8 + warp;
    if (n >= N_TOK) return;

    const float4* x4 = (const float4*)(X + (size_t)n * HDIM);
    const float4* w4 = (const float4*)W_end;
    __nv_bfloat162* xh = (__nv_bfloat162*)(g_xhi + (size_t)n * HDIM);
    __nv_bfloat162* xl = (__nv_bfloat162*)(g_xlo + (size_t)n * HDIM);

    float s = 0.f;
    #pragma unroll 4
    for (int i = lane; i < HDIM / 4; i += 32) {
        float4 a = x4[i];
        float4 b = w4[i];
        s += a.x * b.x + a.y * b.y + a.z * b.z + a.w * b.w;
        __nv_bfloat16 h0 = __float2bfloat16_rn(a.x), h1 = __float2bfloat16_rn(a.y);
        __nv_bfloat16 h2 = __float2bfloat16_rn(a.z), h3 = __float2bfloat16_rn(a.w);
        __nv_bfloat162 H0; H0.x = h0; H0.y = h1;
        __nv_bfloat162 H1; H1.x = h2; H1.y = h3;
        xh[i * 2 + 0] = H0; xh[i * 2 + 1] = H1;
        __nv_bfloat162 L0, L1;
        L0.x = __float2bfloat16_rn(a.x - __bfloat162float(h0));
        L0.y = __float2bfloat16_rn(a.y - __bfloat162float(h1));
        L1.x = __float2bfloat16_rn(a.z - __bfloat162float(h2));
        L1.y = __float2bfloat16_rn(a.w - __bfloat162float(h3));
        xl[i * 2 + 0] = L0; xl[i * 2 + 1] = L1;
    }
    #pragma unroll
    for (int o = 16; o; o >>= 1) s += __shfl_xor_sync(0xffffffffu, s, o);

    float logit = s + b_end[0];
    float ep = 1.f / (1.f + expf(-logit));

    int cls = pY[n];
    float* orow = out + N_TOK + (size_t)n * CCOLS;

    if (cls == 0) {
        for (int j = lane; j < CCOLS; j += 32)
            orow[j] = (j < 2) ? ep : 0.f;
        if (lane == 0) { g_end_prob[n] = ep; out[n] = logf(ep); }
    } else if (cls == 1) {
        for (int j = lane; j < CCOLS; j += 32)
            if (j < 2 || j >= 2 + FPCNT) orow[j] = 0.f;
        if (lane == 0) {
            g_end_prob[n] = ep;
            int r = atomicAdd(&g_cnt[0], 1);
            g_rows[0][r] = n;
        }
    } else {
        for (int j = lane; j < 2 + FPCNT; j += 32)
            orow[j] = 0.f;
        if (lane == 0) {
            g_end_prob[n] = ep;
            int r = atomicAdd(&g_cnt[1], 1);
            g_rows[1][r] = n;
        }
    }
}

// Split both weight matrices into bf16 hi/lo (hcw -> slot 0, roo -> slot 1).
__global__ void k_wconv(const float* __restrict__ Wh, const float* __restrict__ Wr) {
    size_t i = (size_t)blockIdx.x * blockDim.x + threadIdx.x;   // per float4
    const size_t tot = (size_t)2 * 1024 * HDIM / 4;
    if (i >= tot) return;
    const float4* src = (i < tot / 2) ? (const float4*)Wh : (const float4*)Wr;
    size_t j = (i < tot / 2) ? i : i - tot / 2;
    float4 v = src[j];
    __nv_bfloat16 h0 = __float2bfloat16_rn(v.x), h1 = __float2bfloat16_rn(v.y);
    __nv_bfloat16 h2 = __float2bfloat16_rn(v.z), h3 = __float2bfloat16_rn(v.w);
    __nv_bfloat162 H0; H0.x = h0; H0.y = h1;
    __nv_bfloat162 H1; H1.x = h2; H1.y = h3;
    __nv_bfloat162 L0, L1;
    L0.x = __float2bfloat16_rn(v.x - __bfloat162float(h0));
    L0.y = __float2bfloat16_rn(v.y - __bfloat162float(h1));
    L1.x = __float2bfloat16_rn(v.z - __bfloat162float(h2));
    L1.y = __float2bfloat16_rn(v.w - __bfloat162float(h3));
    ((__nv_bfloat162*)g_whi)[i * 2 + 0] = H0;
    ((__nv_bfloat162*)g_whi)[i * 2 + 1] = H1;
    ((__nv_bfloat162*)g_wlo)[i * 2 + 0] = L0;
    ((__nv_bfloat162*)g_wlo)[i * 2 + 1] = L1;
}

// ---------------- HMMA (mma.sync) GEMM ----------------
// Tile: M=128 gathered rows x N=128 cols, BK=32, 4-stage cp.async pipeline.
// 8 warps, warp tile 32x64. 3 bf16 passes (AhBh + AhBl + AlBh) ~ fp32 accuracy.
// SMEM per stage: 4 matrices (Ah,Al,Bh,Bl), each 128 rows x 64B data at
// pitch 80B (stride 80 mod 128 covers all eight 16B slots -> ldmatrix
// conflict-free). Stage = 40960B, 4 stages + 512B row cache = 164352B.
#define PITCH   80
#define MATB    10240
#define STAGEB  40960
#define OFF_ROWS 163840
#define SMEM_SZ  164352

__global__ __launch_bounds__(256) void k_gemm_mma(const float* __restrict__ b_hcw,
                                                  const float* __restrict__ b_roo) {
    int cls = blockIdx.z;
    int cnt = g_cnt[cls];
    int m0 = blockIdx.x * 128;
    if (m0 >= cnt) return;
    int n0 = blockIdx.y * 128;

    const __nv_bfloat16* Whi = g_whi + (size_t)cls * 1024 * HDIM;
    const __nv_bfloat16* Wlo = g_wlo + (size_t)cls * 1024 * HDIM;
    const float* bias = cls ? b_roo : b_hcw;

    extern __shared__ char smem[];
    uint32_t sb = smem_to_u32(smem);
    int tid = threadIdx.x;
    int lane = tid & 31, wid = tid >> 5;
    int wm = wid >> 1, wn = wid & 1;          // warp grid 4(m) x 2(n)

    int* s_arow = (int*)(smem + OFF_ROWS);
    if (tid < 128) s_arow[tid] = g_rows[cls][min(m0 + tid, cnt - 1)];
    __syncthreads();

    // Per-thread cp.async descriptors: 8 chunks of 16B per stage.
    // chunk c = tid + i*256: mat = c>>9, row = (c&511)>>2, cv = (c&511)&3
    const __nv_bfloat16* gbase[8];
    uint32_t soff[8];
    #pragma unroll
    for (int i = 0; i < 8; i++) {
        int c = tid + i * 256;
        int mat = c >> 9, rc = c & 511, row = rc >> 2, cv = rc & 3;
        const __nv_bfloat16* g;
        if (mat == 0)      g = g_xhi + (size_t)s_arow[row] * HDIM;
        else if (mat == 1) g = g_xlo + (size_t)s_arow[row] * HDIM;
        else if (mat == 2) g = Whi + (size_t)(n0 + row) * HDIM;
        else               g = Wlo + (size_t)(n0 + row) * HDIM;
        gbase[i] = g + cv * 8;
        soff[i] = (uint32_t)(mat * MATB + row * PITCH + cv * 16);
    }

    float acc[2][8][4];
    #pragma unroll
    for (int a = 0; a < 2; a++)
        #pragma unroll
        for (int b = 0; b < 8; b++)
            #pragma unroll
            for (int c = 0; c < 4; c++) acc[a][b][c] = 0.f;

    #define LOAD_STAGE(kc, buf) do {                         \
        int _ke = (kc) * 32;                                 \
        uint32_t _stb = sb + (uint32_t)(buf) * STAGEB;       \
        _Pragma("unroll")                                    \
        for (int _i = 0; _i < 8; _i++) {                     \
            const void* _ga = gbase[_i] + _ke;               \
            CP_ASYNC16(_stb + soff[_i], _ga);                \
        }                                                    \
        CP_COMMIT();                                         \
    } while (0)

    LOAD_STAGE(0, 0);
    LOAD_STAGE(1, 1);
    LOAD_STAGE(2, 2);

    #pragma unroll 1
    for (int kc = 0; kc < HDIM / 32; kc++) {
        CP_WAIT(2);
        __syncthreads();
        if (kc + 3 < HDIM / 32) LOAD_STAGE(kc + 3, (kc + 3) & 3);

        uint32_t stb = sb + (uint32_t)(kc & 3) * STAGEB;
        #pragma unroll
        for (int kk = 0; kk < 2; kk++) {
            uint32_t kb = kk * 32;
            uint32_t ah[2][4], al[2][4];
            uint32_t cbA = kb + ((lane >> 4) & 1) * 16;
            #pragma unroll
            for (int mt = 0; mt < 2; mt++) {
                uint32_t r = wm * 32 + mt * 16 + (lane & 15);
                ldsm4(ah[mt], stb + 0    + r * PITCH + cbA);
                ldsm4(al[mt], stb + MATB + r * PITCH + cbA);
            }
            uint32_t rB = wn * 64 + (lane & 7) + ((lane >> 4) & 1) * 8;
            uint32_t cB = kb + ((lane >> 3) & 1) * 16;
            #pragma unroll
            for (int p = 0; p < 4; p++) {
                uint32_t bh[4], bl[4];
                ldsm4(bh, stb + 2 * MATB + (rB + p * 16) * PITCH + cB);
                ldsm4(bl, stb + 3 * MATB + (rB + p * 16) * PITCH + cB);
                #pragma unroll
                for (int mt = 0; mt < 2; mt++) {
                    mma16816(acc[mt][2 * p],     ah[mt], bh);
                    mma16816(acc[mt][2 * p + 1], ah[mt], bh + 2);
                    mma16816(acc[mt][2 * p],     ah[mt], bl);
                    mma16816(acc[mt][2 * p + 1], ah[mt], bl + 2);
                    mma16816(acc[mt][2 * p],     al[mt], bh);
                    mma16816(acc[mt][2 * p + 1], al[mt], bh + 2);
                }
            }
        }
    }
    CP_WAIT(0);

    // Epilogue: scatter logits + bias
    int gi = lane >> 2, ci = (lane & 3) * 2;
    #pragma unroll
    for (int mt = 0; mt < 2; mt++) {
        int lr = wm * 32 + mt * 16 + gi;
        bool ok0 = (m0 + lr) < cnt;
        bool ok1 = (m0 + lr + 8) < cnt;
        float* d0 = g_logits + (size_t)s_arow[lr] * 1024;
        float* d1 = g_logits + (size_t)s_arow[lr + 8] * 1024;
        #pragma unroll
        for (int nt = 0; nt < 8; nt++) {
            int ncol = n0 + wn * 64 + nt * 8 + ci;
            float bb0 = bias[ncol], bb1 = bias[ncol + 1];
            if (ok0) {
                float2 v; v.x = acc[mt][nt][0] + bb0; v.y = acc[mt][nt][1] + bb1;
                *(float2*)(d0 + ncol) = v;
            }
            if (ok1) {
                float2 v; v.x = acc[mt][nt][2] + bb0; v.y = acc[mt][nt][3] + bb1;
                *(float2*)(d1 + ncol) = v;
            }
        }
    }
}

// One CTA per compacted row: softmax over 1024 logits, scale by (1-end_prob),
// scatter into the active output segment, gather log-prob at Y.
__global__ __launch_bounds__(256) void k_softmax(const int* __restrict__ Y,
                                                 float* __restrict__ out) {
    int cls = blockIdx.y;
    int cnt = g_cnt[cls];
    int r = blockIdx.x;
    if (r >= cnt) return;
    int n = g_rows[cls][r];

    const float4* L = (const float4*)(g_logits + (size_t)n * 1024);
    int tid = threadIdx.x;
    float4 lv = L[tid];

    __shared__ float red[256];
    float m = fmaxf(fmaxf(lv.x, lv.y), fmaxf(lv.z, lv.w));
    red[tid] = m;
    __syncthreads();
    #pragma unroll
    for (int s = 128; s; s >>= 1) {
        if (tid < s) red[tid] = fmaxf(red[tid], red[tid + s]);
        __syncthreads();
    }
    float mx = red[0];
    __syncthreads();

    float e0 = expf(lv.x - mx), e1 = expf(lv.y - mx);
    float e2 = expf(lv.z - mx), e3 = expf(lv.w - mx);
    red[tid] = e0 + e1 + e2 + e3;
    __syncthreads();
    #pragma unroll
    for (int s = 128; s; s >>= 1) {
        if (tid < s) red[tid] += red[tid + s];
        __syncthreads();
    }
    float inv = 1.f / red[0];
    float ne = 1.f - g_end_prob[n];
    float sc = inv * ne;

    float p0 = e0 * sc, p1 = e1 * sc, p2 = e2 * sc, p3 = e3 * sc;
    float* dst = out + N_TOK + (size_t)n * CCOLS + (cls ? (2 + FPCNT) : 2);
    int j = tid * 4;
    dst[j + 0] = p0; dst[j + 1] = p1; dst[j + 2] = p2; dst[j + 3] = p3;

    int yv = Y[n];
    int idx = cls ? (yv - 2 - FPCNT) : (yv - 2);
    idx = max(0, min(idx, 1023));
    if (idx >= j && idx < j + 4) {
        float p = (idx == j) ? p0 : (idx == j + 1) ? p1 : (idx == j + 2) ? p2 : p3;
        out[n] = logf(p);
    }
}

extern "C" void kernel_launch(void* const* d_in, const int* in_sizes, int n_in,
                              void* d_out, int out_size) {
    const float* X     = (const float*)d_in[0];
    const int*   pY    = (const int*)d_in[1];
    const int*   Y     = (const int*)d_in[2];
    const float* W_end = (const float*)d_in[3];
    const float* b_end = (const float*)d_in[4];
    const float* W_hcw = (const float*)d_in[5];
    const float* b_hcw = (const float*)d_in[6];
    const float* W_roo = (const float*)d_in[7];
    const float* b_roo = (const float*)d_in[8];
    float* out = (float*)d_out;

    cudaFuncSetAttribute(k_gemm_mma, cudaFuncAttributeMaxDynamicSharedMemorySize, SMEM_SZ);

    k_init<<<1, 1>>>();
    k_classify<<<N_TOK / 8, 256>>>(X, pY, W_end, b_end, out);
    k_wconv<<<(2 * 1024 * HDIM / 4 + 255) / 256, 256>>>(W_hcw, W_roo);
    k_gemm_mma<<<dim3(N_TOK / 128, 1024 / 128, 2), 256, SMEM_SZ>>>(b_hcw, b_roo);
    k_softmax<<<dim3(N_TOK, 2), 256>>>(Y, out);
}

// round 8
// speedup vs baseline: 2.2204x; 1.0687x over previous
#include <cuda_runtime.h>
#include <cuda_bf16.h>
#include <math.h>
#include <cstdint>

// Problem constants
#define N_TOK 16384      // B*S = 32*512
#define HDIM  2048
#define FPCNT 1024
#define SPCNT 1024
#define CCOLS 2050       // 2 + FP + SP

// ---------------- device scratch (allocation-free) ----------------
__device__ float g_end_prob[N_TOK];
__device__ int   g_rows[2][N_TOK];
__device__ int   g_cnt[2];
__device__ float g_logits[(size_t)N_TOK * 1024];
__device__ __align__(16) __nv_bfloat16 g_xhi[(size_t)N_TOK * HDIM];
__device__ __align__(16) __nv_bfloat16 g_xlo[(size_t)N_TOK * HDIM];
__device__ __align__(16) __nv_bfloat16 g_whi[(size_t)2 * 1024 * HDIM];
__device__ __align__(16) __nv_bfloat16 g_wlo[(size_t)2 * 1024 * HDIM];

// ---------------- helpers ----------------
__device__ __forceinline__ uint32_t smem_to_u32(const void* p) {
    uint32_t a;
    asm("{ .reg .u64 t; cvta.to.shared.u64 t, %1; cvt.u32.u64 %0, t; }" : "=r"(a) : "l"(p));
    return a;
}

__device__ __forceinline__ void ldsm4(uint32_t* r, uint32_t addr) {
    asm volatile("ldmatrix.sync.aligned.m8n8.x4.shared.b16 {%0,%1,%2,%3}, [%4];"
                 : "=r"(r[0]), "=r"(r[1]), "=r"(r[2]), "=r"(r[3]) : "r"(addr));
}

__device__ __forceinline__ void mma16816(float* c, const uint32_t* a, const uint32_t* b) {
    asm volatile(
        "mma.sync.aligned.m16n8k16.row.col.f32.bf16.bf16.f32 "
        "{%0,%1,%2,%3}, {%4,%5,%6,%7}, {%8,%9}, {%0,%1,%2,%3};"
        : "+f"(c[0]), "+f"(c[1]), "+f"(c[2]), "+f"(c[3])
        : "r"(a[0]), "r"(a[1]), "r"(a[2]), "r"(a[3]), "r"(b[0]), "r"(b[1]));
}

#define CP_ASYNC16(sa, ga) \
    asm volatile("cp.async.cg.shared.global [%0], [%1], 16;" :: "r"(sa), "l"(ga))
#define CP_COMMIT()  asm volatile("cp.async.commit_group;" ::: "memory")
#define CP_WAIT(n)   asm volatile("cp.async.wait_group %0;" :: "n"(n) : "memory")

// ---------------- kernels ----------------
__global__ void k_init() { g_cnt[0] = 0; g_cnt[1] = 0; }

// One warp per token: end-head GEMV + sigmoid, zero-fill inactive output
// segments, compact rows per class, AND emit bf16 hi/lo split of X.
__global__ void k_classify(const float* __restrict__ X,
                           const int* __restrict__ pY,
                           const float* __restrict__ W_end,
                           const float* __restrict__ b_end,
                           float* __restrict__ out) {
    int warp = threadIdx.x >> 5;
    int lane = threadIdx.x & 31;
    int n = blockIdx.x * 8 + warp;
    if (n >= N_TOK) return;

    const float4* x4 = (const float4*)(X + (size_t)n * HDIM);
    const float4* w4 = (const float4*)W_end;
    __nv_bfloat162* xh = (__nv_bfloat162*)(g_xhi + (size_t)n * HDIM);
    __nv_bfloat162* xl = (__nv_bfloat162*)(g_xlo + (size_t)n * HDIM);

    float s = 0.f;
    #pragma unroll 4
    for (int i = lane; i < HDIM / 4; i += 32) {
        float4 a = x4[i];
        float4 b = w4[i];
        s += a.x * b.x + a.y * b.y + a.z * b.z + a.w * b.w;
        __nv_bfloat16 h0 = __float2bfloat16_rn(a.x), h1 = __float2bfloat16_rn(a.y);
        __nv_bfloat16 h2 = __float2bfloat16_rn(a.z), h3 = __float2bfloat16_rn(a.w);
        __nv_bfloat162 H0; H0.x = h0; H0.y = h1;
        __nv_bfloat162 H1; H1.x = h2; H1.y = h3;
        xh[i * 2 + 0] = H0; xh[i * 2 + 1] = H1;
        __nv_bfloat162 L0, L1;
        L0.x = __float2bfloat16_rn(a.x - __bfloat162float(h0));
        L0.y = __float2bfloat16_rn(a.y - __bfloat162float(h1));
        L1.x = __float2bfloat16_rn(a.z - __bfloat162float(h2));
        L1.y = __float2bfloat16_rn(a.w - __bfloat162float(h3));
        xl[i * 2 + 0] = L0; xl[i * 2 + 1] = L1;
    }
    #pragma unroll
    for (int o = 16; o; o >>= 1) s += __shfl_xor_sync(0xffffffffu, s, o);

    float logit = s + b_end[0];
    float ep = 1.f / (1.f + expf(-logit));

    int cls = pY[n];
    float* orow = out + N_TOK + (size_t)n * CCOLS;

    if (cls == 0) {
        for (int j = lane; j < CCOLS; j += 32)
            orow[j] = (j < 2) ? ep : 0.f;
        if (lane == 0) { g_end_prob[n] = ep; out[n] = logf(ep); }
    } else if (cls == 1) {
        for (int j = lane; j < CCOLS; j += 32)
            if (j < 2 || j >= 2 + FPCNT) orow[j] = 0.f;
        if (lane == 0) {
            g_end_prob[n] = ep;
            int r = atomicAdd(&g_cnt[0], 1);
            g_rows[0][r] = n;
        }
    } else {
        for (int j = lane; j < 2 + FPCNT; j += 32)
            orow[j] = 0.f;
        if (lane == 0) {
            g_end_prob[n] = ep;
            int r = atomicAdd(&g_cnt[1], 1);
            g_rows[1][r] = n;
        }
    }
}

// Split both weight matrices into bf16 hi/lo (hcw -> slot 0, roo -> slot 1).
__global__ void k_wconv(const float* __restrict__ Wh, const float* __restrict__ Wr) {
    size_t i = (size_t)blockIdx.x * blockDim.x + threadIdx.x;   // per float4
    const size_t tot = (size_t)2 * 1024 * HDIM / 4;
    if (i >= tot) return;
    const float4* src = (i < tot / 2) ? (const float4*)Wh : (const float4*)Wr;
    size_t j = (i < tot / 2) ? i : i - tot / 2;
    float4 v = src[j];
    __nv_bfloat16 h0 = __float2bfloat16_rn(v.x), h1 = __float2bfloat16_rn(v.y);
    __nv_bfloat16 h2 = __float2bfloat16_rn(v.z), h3 = __float2bfloat16_rn(v.w);
    __nv_bfloat162 H0; H0.x = h0; H0.y = h1;
    __nv_bfloat162 H1; H1.x = h2; H1.y = h3;
    __nv_bfloat162 L0, L1;
    L0.x = __float2bfloat16_rn(v.x - __bfloat162float(h0));
    L0.y = __float2bfloat16_rn(v.y - __bfloat162float(h1));
    L1.x = __float2bfloat16_rn(v.z - __bfloat162float(h2));
    L1.y = __float2bfloat16_rn(v.w - __bfloat162float(h3));
    ((__nv_bfloat162*)g_whi)[i * 2 + 0] = H0;
    ((__nv_bfloat162*)g_whi)[i * 2 + 1] = H1;
    ((__nv_bfloat162*)g_wlo)[i * 2 + 0] = L0;
    ((__nv_bfloat162*)g_wlo)[i * 2 + 1] = L1;
}

// ---------------- HMMA (mma.sync) GEMM ----------------
// Tile: M=128 gathered rows x N=128 cols, BK=32, 4-stage cp.async pipeline.
// 8 warps, warp tile 32x64. 3 bf16 passes (AhBh + AhBl + AlBh) ~ fp32 accuracy.
// MMA scheduling: per B-pair (2 p-tiles) issue the 3 passes as 8-MMA batches
// so dependent writes to one accumulator are >= 8 MMAs apart (hides HMMA lat).
#define PITCH   80
#define MATB    10240
#define STAGEB  40960
#define OFF_ROWS 163840
#define SMEM_SZ  164352

__global__ __launch_bounds__(256) void k_gemm_mma(const float* __restrict__ b_hcw,
                                                  const float* __restrict__ b_roo) {
    int cls = blockIdx.z;
    int cnt = g_cnt[cls];
    int m0 = blockIdx.x * 128;
    if (m0 >= cnt) return;
    int n0 = blockIdx.y * 128;

    const __nv_bfloat16* Whi = g_whi + (size_t)cls * 1024 * HDIM;
    const __nv_bfloat16* Wlo = g_wlo + (size_t)cls * 1024 * HDIM;
    const float* bias = cls ? b_roo : b_hcw;

    extern __shared__ char smem[];
    uint32_t sb = smem_to_u32(smem);
    int tid = threadIdx.x;
    int lane = tid & 31, wid = tid >> 5;
    int wm = wid >> 1, wn = wid & 1;          // warp grid 4(m) x 2(n)

    int* s_arow = (int*)(smem + OFF_ROWS);
    if (tid < 128) s_arow[tid] = g_rows[cls][min(m0 + tid, cnt - 1)];
    __syncthreads();

    // Per-thread cp.async descriptors: 8 chunks of 16B per stage.
    const __nv_bfloat16* gbase[8];
    uint32_t soff[8];
    #pragma unroll
    for (int i = 0; i < 8; i++) {
        int c = tid + i * 256;
        int mat = c >> 9, rc = c & 511, row = rc >> 2, cv = rc & 3;
        const __nv_bfloat16* g;
        if (mat == 0)      g = g_xhi + (size_t)s_arow[row] * HDIM;
        else if (mat == 1) g = g_xlo + (size_t)s_arow[row] * HDIM;
        else if (mat == 2) g = Whi + (size_t)(n0 + row) * HDIM;
        else               g = Wlo + (size_t)(n0 + row) * HDIM;
        gbase[i] = g + cv * 8;
        soff[i] = (uint32_t)(mat * MATB + row * PITCH + cv * 16);
    }

    float acc[2][8][4];
    #pragma unroll
    for (int a = 0; a < 2; a++)
        #pragma unroll
        for (int b = 0; b < 8; b++)
            #pragma unroll
            for (int c = 0; c < 4; c++) acc[a][b][c] = 0.f;

    #define LOAD_STAGE(kc, buf) do {                         \
        int _ke = (kc) * 32;                                 \
        uint32_t _stb = sb + (uint32_t)(buf) * STAGEB;       \
        _Pragma("unroll")                                    \
        for (int _i = 0; _i < 8; _i++) {                     \
            const void* _ga = gbase[_i] + _ke;               \
            CP_ASYNC16(_stb + soff[_i], _ga);                \
        }                                                    \
        CP_COMMIT();                                         \
    } while (0)

    LOAD_STAGE(0, 0);
    LOAD_STAGE(1, 1);
    LOAD_STAGE(2, 2);

    #pragma unroll 1
    for (int kc = 0; kc < HDIM / 32; kc++) {
        CP_WAIT(2);
        __syncthreads();
        if (kc + 3 < HDIM / 32) LOAD_STAGE(kc + 3, (kc + 3) & 3);

        uint32_t stb = sb + (uint32_t)(kc & 3) * STAGEB;
        #pragma unroll
        for (int kk = 0; kk < 2; kk++) {
            uint32_t kb = kk * 32;
            uint32_t ah[2][4], al[2][4];
            uint32_t cbA = kb + ((lane >> 4) & 1) * 16;
            #pragma unroll
            for (int mt = 0; mt < 2; mt++) {
                uint32_t r = wm * 32 + mt * 16 + (lane & 15);
                ldsm4(ah[mt], stb + 0    + r * PITCH + cbA);
                ldsm4(al[mt], stb + MATB + r * PITCH + cbA);
            }
            uint32_t rB = wn * 64 + (lane & 7) + ((lane >> 4) & 1) * 8;
            uint32_t cB = kb + ((lane >> 3) & 1) * 16;
            #pragma unroll
            for (int pp = 0; pp < 2; pp++) {
                uint32_t bh[2][4], bl[2][4];
                #pragma unroll
                for (int q = 0; q < 2; q++) {
                    int p = pp * 2 + q;
                    ldsm4(bh[q], stb + 2 * MATB + (rB + p * 16) * PITCH + cB);
                    ldsm4(bl[q], stb + 3 * MATB + (rB + p * 16) * PITCH + cB);
                }
                // pass 1: ah x bh  (8 independent MMAs)
                #pragma unroll
                for (int mt = 0; mt < 2; mt++)
                    #pragma unroll
                    for (int q = 0; q < 2; q++) {
                        int p = pp * 2 + q;
                        mma16816(acc[mt][2 * p],     ah[mt], bh[q]);
                        mma16816(acc[mt][2 * p + 1], ah[mt], bh[q] + 2);
                    }
                // pass 2: ah x bl  (8 MMAs, distance 8 from pass 1)
                #pragma unroll
                for (int mt = 0; mt < 2; mt++)
                    #pragma unroll
                    for (int q = 0; q < 2; q++) {
                        int p = pp * 2 + q;
                        mma16816(acc[mt][2 * p],     ah[mt], bl[q]);
                        mma16816(acc[mt][2 * p + 1], ah[mt], bl[q] + 2);
                    }
                // pass 3: al x bh  (8 MMAs, distance 8 from pass 2)
                #pragma unroll
                for (int mt = 0; mt < 2; mt++)
                    #pragma unroll
                    for (int q = 0; q < 2; q++) {
                        int p = pp * 2 + q;
                        mma16816(acc[mt][2 * p],     al[mt], bh[q]);
                        mma16816(acc[mt][2 * p + 1], al[mt], bh[q] + 2);
                    }
            }
        }
    }
    CP_WAIT(0);

    // Epilogue: scatter logits + bias
    int gi = lane >> 2, ci = (lane & 3) * 2;
    #pragma unroll
    for (int mt = 0; mt < 2; mt++) {
        int lr = wm * 32 + mt * 16 + gi;
        bool ok0 = (m0 + lr) < cnt;
        bool ok1 = (m0 + lr + 8) < cnt;
        float* d0 = g_logits + (size_t)s_arow[lr] * 1024;
        float* d1 = g_logits + (size_t)s_arow[lr + 8] * 1024;
        #pragma unroll
        for (int nt = 0; nt < 8; nt++) {
            int ncol = n0 + wn * 64 + nt * 8 + ci;
            float bb0 = bias[ncol], bb1 = bias[ncol + 1];
            if (ok0) {
                float2 v; v.x = acc[mt][nt][0] + bb0; v.y = acc[mt][nt][1] + bb1;
                *(float2*)(d0 + ncol) = v;
            }
            if (ok1) {
                float2 v; v.x = acc[mt][nt][2] + bb0; v.y = acc[mt][nt][3] + bb1;
                *(float2*)(d1 + ncol) = v;
            }
        }
    }
}

// One CTA per compacted row: softmax over 1024 logits (warp-shuffle reductions,
// 2 block syncs), scale by (1-end_prob), scatter, gather log-prob at Y.
__global__ __launch_bounds__(256) void k_softmax(const int* __restrict__ Y,
                                                 float* __restrict__ out) {
    int cls = blockIdx.y;
    int cnt = g_cnt[cls];
    int r = blockIdx.x;
    if (r >= cnt) return;
    int n = g_rows[cls][r];

    const float4* L = (const float4*)(g_logits + (size_t)n * 1024);
    int tid = threadIdx.x;
    int lane = tid & 31, warp = tid >> 5;
    float4 lv = L[tid];

    __shared__ float wmax[8], wsum[8];

    float m = fmaxf(fmaxf(lv.x, lv.y), fmaxf(lv.z, lv.w));
    #pragma unroll
    for (int o = 16; o; o >>= 1) m = fmaxf(m, __shfl_xor_sync(0xffffffffu, m, o));
    if (lane == 0) wmax[warp] = m;
    __syncthreads();
    float mx = wmax[0];
    #pragma unroll
    for (int i = 1; i < 8; i++) mx = fmaxf(mx, wmax[i]);

    float e0 = expf(lv.x - mx), e1 = expf(lv.y - mx);
    float e2 = expf(lv.z - mx), e3 = expf(lv.w - mx);
    float s = e0 + e1 + e2 + e3;
    #pragma unroll
    for (int o = 16; o; o >>= 1) s += __shfl_xor_sync(0xffffffffu, s, o);
    if (lane == 0) wsum[warp] = s;
    __syncthreads();
    float tot = wsum[0];
    #pragma unroll
    for (int i = 1; i < 8; i++) tot += wsum[i];

    float inv = 1.f / tot;
    float ne = 1.f - g_end_prob[n];
    float sc = inv * ne;

    float p0 = e0 * sc, p1 = e1 * sc, p2 = e2 * sc, p3 = e3 * sc;
    float* dst = out + N_TOK + (size_t)n * CCOLS + (cls ? (2 + FPCNT) : 2);
    int j = tid * 4;
    dst[j + 0] = p0; dst[j + 1] = p1; dst[j + 2] = p2; dst[j + 3] = p3;

    int yv = Y[n];
    int idx = cls ? (yv - 2 - FPCNT) : (yv - 2);
    idx = max(0, min(idx, 1023));
    if (idx >= j && idx < j + 4) {
        float p = (idx == j) ? p0 : (idx == j + 1) ? p1 : (idx == j + 2) ? p2 : p3;
        out[n] = logf(p);
    }
}

extern "C" void kernel_launch(void* const* d_in, const int* in_sizes, int n_in,
                              void* d_out, int out_size) {
    const float* X     = (const float*)d_in[0];
    const int*   pY    = (const int*)d_in[1];
    const int*   Y     = (const int*)d_in[2];
    const float* W_end = (const float*)d_in[3];
    const float* b_end = (const float*)d_in[4];
    const float* W_hcw = (const float*)d_in[5];
    const float* b_hcw = (const float*)d_in[6];
    const float* W_roo = (const float*)d_in[7];
    const float* b_roo = (const float*)d_in[8];
    float* out = (float*)d_out;

    cudaFuncSetAttribute(k_gemm_mma, cudaFuncAttributeMaxDynamicSharedMemorySize, SMEM_SZ);

    k_init<<<1, 1>>>();
    k_classify<<<N_TOK / 8, 256>>>(X, pY, W_end, b_end, out);
    k_wconv<<<(2 * 1024 * HDIM / 4 + 255) / 256, 256>>>(W_hcw, W_roo);
    k_gemm_mma<<<dim3(N_TOK / 128, 1024 / 128, 2), 256, SMEM_SZ>>>(b_hcw, b_roo);
    k_softmax<<<dim3(N_TOK, 2), 256>>>(Y, out);
}

// round 12
// speedup vs baseline: 2.3862x; 1.0747x over previous
#include <cuda_runtime.h>
#include <cuda_bf16.h>
#include <math.h>
#include <cstdint>

// Problem constants
#define N_TOK 16384      // B*S = 32*512
#define HDIM  2048
#define FPCNT 1024
#define SPCNT 1024
#define CCOLS 2050       // 2 + FP + SP

// ---------------- device scratch (allocation-free) ----------------
__device__ float g_end_prob[N_TOK];
__device__ int   g_rows[2][N_TOK];
__device__ int   g_cnt[2];
__device__ float g_logits[(size_t)N_TOK * 1024];
__device__ __align__(16) __nv_bfloat16 g_xhi[(size_t)N_TOK * HDIM];
__device__ __align__(16) __nv_bfloat16 g_xlo[(size_t)N_TOK * HDIM];
__device__ __align__(16) __nv_bfloat16 g_whi[(size_t)2 * 1024 * HDIM];
__device__ __align__(16) __nv_bfloat16 g_wlo[(size_t)2 * 1024 * HDIM];

// ---------------- helpers ----------------
__device__ __forceinline__ uint32_t smem_to_u32(const void* p) {
    uint32_t a;
    asm("{ .reg .u64 t; cvta.to.shared.u64 t, %1; cvt.u32.u64 %0, t; }" : "=r"(a) : "l"(p));
    return a;
}

__device__ __forceinline__ void ldsm4(uint32_t* r, uint32_t addr) {
    asm volatile("ldmatrix.sync.aligned.m8n8.x4.shared.b16 {%0,%1,%2,%3}, [%4];"
                 : "=r"(r[0]), "=r"(r[1]), "=r"(r[2]), "=r"(r[3]) : "r"(addr));
}

__device__ __forceinline__ void mma16816(float* c, const uint32_t* a, const uint32_t* b) {
    asm volatile(
        "mma.sync.aligned.m16n8k16.row.col.f32.bf16.bf16.f32 "
        "{%0,%1,%2,%3}, {%4,%5,%6,%7}, {%8,%9}, {%0,%1,%2,%3};"
        : "+f"(c[0]), "+f"(c[1]), "+f"(c[2]), "+f"(c[3])
        : "r"(a[0]), "r"(a[1]), "r"(a[2]), "r"(a[3]), "r"(b[0]), "r"(b[1]));
}

#define CP_ASYNC16(sa, ga) \
    asm volatile("cp.async.cg.shared.global [%0], [%1], 16;" :: "r"(sa), "l"(ga))
#define CP_COMMIT()  asm volatile("cp.async.commit_group;" ::: "memory")
#define CP_WAIT(n)   asm volatile("cp.async.wait_group %0;" :: "n"(n) : "memory")

// ---------------- kernels ----------------
__global__ void k_init() { g_cnt[0] = 0; g_cnt[1] = 0; }

// One warp per token: end-head GEMV + sigmoid, zero-fill inactive output
// segments, compact rows per class, AND emit bf16 hi/lo split of X.
__global__ void k_classify(const float* __restrict__ X,
                           const int* __restrict__ pY,
                           const float* __restrict__ W_end,
                           const float* __restrict__ b_end,
                           float* __restrict__ out) {
    int warp = threadIdx.x >> 5;
    int lane = threadIdx.x & 31;
    int n = blockIdx.x * 8 + warp;
    if (n >= N_TOK) return;

    const float4* x4 = (const float4*)(X + (size_t)n * HDIM);
    const float4* w4 = (const float4*)W_end;
    __nv_bfloat162* xh = (__nv_bfloat162*)(g_xhi + (size_t)n * HDIM);
    __nv_bfloat162* xl = (__nv_bfloat162*)(g_xlo + (size_t)n * HDIM);

    float s = 0.f;
    #pragma unroll 4
    for (int i = lane; i < HDIM / 4; i += 32) {
        float4 a = x4[i];
        float4 b = w4[i];
        s += a.x * b.x + a.y * b.y + a.z * b.z + a.w * b.w;
        __nv_bfloat16 h0 = __float2bfloat16_rn(a.x), h1 = __float2bfloat16_rn(a.y);
        __nv_bfloat16 h2 = __float2bfloat16_rn(a.z), h3 = __float2bfloat16_rn(a.w);
        __nv_bfloat162 H0; H0.x = h0; H0.y = h1;
        __nv_bfloat162 H1; H1.x = h2; H1.y = h3;
        xh[i * 2 + 0] = H0; xh[i * 2 + 1] = H1;
        __nv_bfloat162 L0, L1;
        L0.x = __float2bfloat16_rn(a.x - __bfloat162float(h0));
        L0.y = __float2bfloat16_rn(a.y - __bfloat162float(h1));
        L1.x = __float2bfloat16_rn(a.z - __bfloat162float(h2));
        L1.y = __float2bfloat16_rn(a.w - __bfloat162float(h3));
        xl[i * 2 + 0] = L0; xl[i * 2 + 1] = L1;
    }
    #pragma unroll
    for (int o = 16; o; o >>= 1) s += __shfl_xor_sync(0xffffffffu, s, o);

    float logit = s + b_end[0];
    float ep = 1.f / (1.f + expf(-logit));

    int cls = pY[n];
    float* orow = out + N_TOK + (size_t)n * CCOLS;

    if (cls == 0) {
        for (int j = lane; j < CCOLS; j += 32)
            orow[j] = (j < 2) ? ep : 0.f;
        if (lane == 0) { g_end_prob[n] = ep; out[n] = logf(ep); }
    } else if (cls == 1) {
        for (int j = lane; j < CCOLS; j += 32)
            if (j < 2 || j >= 2 + FPCNT) orow[j] = 0.f;
        if (lane == 0) {
            g_end_prob[n] = ep;
            int r = atomicAdd(&g_cnt[0], 1);
            g_rows[0][r] = n;
        }
    } else {
        for (int j = lane; j < 2 + FPCNT; j += 32)
            orow[j] = 0.f;
        if (lane == 0) {
            g_end_prob[n] = ep;
            int r = atomicAdd(&g_cnt[1], 1);
            g_rows[1][r] = n;
        }
    }
}

// Split both weight matrices into bf16 hi/lo (hcw -> slot 0, roo -> slot 1).
__global__ void k_wconv(const float* __restrict__ Wh, const float* __restrict__ Wr) {
    size_t i = (size_t)blockIdx.x * blockDim.x + threadIdx.x;   // per float4
    const size_t tot = (size_t)2 * 1024 * HDIM / 4;
    if (i >= tot) return;
    const float4* src = (i < tot / 2) ? (const float4*)Wh : (const float4*)Wr;
    size_t j = (i < tot / 2) ? i : i - tot / 2;
    float4 v = src[j];
    __nv_bfloat16 h0 = __float2bfloat16_rn(v.x), h1 = __float2bfloat16_rn(v.y);
    __nv_bfloat16 h2 = __float2bfloat16_rn(v.z), h3 = __float2bfloat16_rn(v.w);
    __nv_bfloat162 H0; H0.x = h0; H0.y = h1;
    __nv_bfloat162 H1; H1.x = h2; H1.y = h3;
    __nv_bfloat162 L0, L1;
    L0.x = __float2bfloat16_rn(v.x - __bfloat162float(h0));
    L0.y = __float2bfloat16_rn(v.y - __bfloat162float(h1));
    L1.x = __float2bfloat16_rn(v.z - __bfloat162float(h2));
    L1.y = __float2bfloat16_rn(v.w - __bfloat162float(h3));
    ((__nv_bfloat162*)g_whi)[i * 2 + 0] = H0;
    ((__nv_bfloat162*)g_whi)[i * 2 + 1] = H1;
    ((__nv_bfloat162*)g_wlo)[i * 2 + 0] = L0;
    ((__nv_bfloat162*)g_wlo)[i * 2 + 1] = L1;
}

// ---------------- HMMA (mma.sync) GEMM ----------------
// Tile: M=128 gathered rows x N=128 cols, BK=32, 2-stage cp.async pipeline
// (82KB smem -> 2 CTAs/SM, 16 warps: cross-CTA desync keeps tensor pipe fed).
// 8 warps, warp tile 32x64. 3 bf16 passes (AhBh + AhBl + AlBh) ~ fp32 accuracy.
#define PITCH   80
#define MATB    10240
#define STAGEB  40960
#define OFF_ROWS 81920
#define SMEM_SZ  82432

__global__ __launch_bounds__(256, 2) void k_gemm_mma(const float* __restrict__ b_hcw,
                                                     const float* __restrict__ b_roo) {
    int cls = blockIdx.z;
    int cnt = g_cnt[cls];
    int m0 = blockIdx.x * 128;
    if (m0 >= cnt) return;
    int n0 = blockIdx.y * 128;

    const __nv_bfloat16* Whi = g_whi + (size_t)cls * 1024 * HDIM;
    const __nv_bfloat16* Wlo = g_wlo + (size_t)cls * 1024 * HDIM;
    const float* bias = cls ? b_roo : b_hcw;

    extern __shared__ char smem[];
    uint32_t sb = smem_to_u32(smem);
    int tid = threadIdx.x;
    int lane = tid & 31, wid = tid >> 5;
    int wm = wid >> 1, wn = wid & 1;          // warp grid 4(m) x 2(n)

    int* s_arow = (int*)(smem + OFF_ROWS);
    if (tid < 128) s_arow[tid] = g_rows[cls][min(m0 + tid, cnt - 1)];
    __syncthreads();

    // Per-thread cp.async descriptors: 8 chunks of 16B per stage.
    const __nv_bfloat16* gbase[8];
    uint32_t soff[8];
    #pragma unroll
    for (int i = 0; i < 8; i++) {
        int c = tid + i * 256;
        int mat = c >> 9, rc = c & 511, row = rc >> 2, cv = rc & 3;
        const __nv_bfloat16* g;
        if (mat == 0)      g = g_xhi + (size_t)s_arow[row] * HDIM;
        else if (mat == 1) g = g_xlo + (size_t)s_arow[row] * HDIM;
        else if (mat == 2) g = Whi + (size_t)(n0 + row) * HDIM;
        else               g = Wlo + (size_t)(n0 + row) * HDIM;
        gbase[i] = g + cv * 8;
        soff[i] = (uint32_t)(mat * MATB + row * PITCH + cv * 16);
    }

    float acc[2][8][4];
    #pragma unroll
    for (int a = 0; a < 2; a++)
        #pragma unroll
        for (int b = 0; b < 8; b++)
            #pragma unroll
            for (int c = 0; c < 4; c++) acc[a][b][c] = 0.f;

    #define LOAD_STAGE(kc, buf) do {                         \
        int _ke = (kc) * 32;                                 \
        uint32_t _stb = sb + (uint32_t)(buf) * STAGEB;       \
        _Pragma("unroll")                                    \
        for (int _i = 0; _i < 8; _i++) {                     \
            const void* _ga = gbase[_i] + _ke;               \
            CP_ASYNC16(_stb + soff[_i], _ga);                \
        }                                                    \
        CP_COMMIT();                                         \
    } while (0)

    LOAD_STAGE(0, 0);
    LOAD_STAGE(1, 1);

    #pragma unroll 1
    for (int kc = 0; kc < HDIM / 32; kc++) {
        CP_WAIT(1);          // stage kc resident (kc+1 may still be in flight)
        __syncthreads();

        uint32_t stb = sb + (uint32_t)(kc & 1) * STAGEB;
        #pragma unroll
        for (int kk = 0; kk < 2; kk++) {
            uint32_t kb = kk * 32;
            uint32_t ah[2][4], al[2][4];
            uint32_t cbA = kb + ((lane >> 4) & 1) * 16;
            #pragma unroll
            for (int mt = 0; mt < 2; mt++) {
                uint32_t r = wm * 32 + mt * 16 + (lane & 15);
                ldsm4(ah[mt], stb + 0    + r * PITCH + cbA);
                ldsm4(al[mt], stb + MATB + r * PITCH + cbA);
            }
            uint32_t rB = wn * 64 + (lane & 7) + ((lane >> 4) & 1) * 8;
            uint32_t cB = kb + ((lane >> 3) & 1) * 16;
            #pragma unroll
            for (int pp = 0; pp < 2; pp++) {
                uint32_t bh[2][4], bl[2][4];
                #pragma unroll
                for (int q = 0; q < 2; q++) {
                    int p = pp * 2 + q;
                    ldsm4(bh[q], stb + 2 * MATB + (rB + p * 16) * PITCH + cB);
                    ldsm4(bl[q], stb + 3 * MATB + (rB + p * 16) * PITCH + cB);
                }
                // pass 1: ah x bh  (8 independent MMAs)
                #pragma unroll
                for (int mt = 0; mt < 2; mt++)
                    #pragma unroll
                    for (int q = 0; q < 2; q++) {
                        int p = pp * 2 + q;
                        mma16816(acc[mt][2 * p],     ah[mt], bh[q]);
                        mma16816(acc[mt][2 * p + 1], ah[mt], bh[q] + 2);
                    }
                // pass 2: ah x bl
                #pragma unroll
                for (int mt = 0; mt < 2; mt++)
                    #pragma unroll
                    for (int q = 0; q < 2; q++) {
                        int p = pp * 2 + q;
                        mma16816(acc[mt][2 * p],     ah[mt], bl[q]);
                        mma16816(acc[mt][2 * p + 1], ah[mt], bl[q] + 2);
                    }
                // pass 3: al x bh
                #pragma unroll
                for (int mt = 0; mt < 2; mt++)
                    #pragma unroll
                    for (int q = 0; q < 2; q++) {
                        int p = pp * 2 + q;
                        mma16816(acc[mt][2 * p],     al[mt], bh[q]);
                        mma16816(acc[mt][2 * p + 1], al[mt], bh[q] + 2);
                    }
            }
        }
        __syncthreads();     // all warps done reading buf (kc&1)
        if (kc + 2 < HDIM / 32) LOAD_STAGE(kc + 2, kc & 1);
    }
    CP_WAIT(0);

    // Epilogue: scatter logits + bias
    int gi = lane >> 2, ci = (lane & 3) * 2;
    #pragma unroll
    for (int mt = 0; mt < 2; mt++) {
        int lr = wm * 32 + mt * 16 + gi;
        bool ok0 = (m0 + lr) < cnt;
        bool ok1 = (m0 + lr + 8) < cnt;
        float* d0 = g_logits + (size_t)s_arow[lr] * 1024;
        float* d1 = g_logits + (size_t)s_arow[lr + 8] * 1024;
        #pragma unroll
        for (int nt = 0; nt < 8; nt++) {
            int ncol = n0 + wn * 64 + nt * 8 + ci;
            float bb0 = bias[ncol], bb1 = bias[ncol + 1];
            if (ok0) {
                float2 v; v.x = acc[mt][nt][0] + bb0; v.y = acc[mt][nt][1] + bb1;
                *(float2*)(d0 + ncol) = v;
            }
            if (ok1) {
                float2 v; v.x = acc[mt][nt][2] + bb0; v.y = acc[mt][nt][3] + bb1;
                *(float2*)(d1 + ncol) = v;
            }
        }
    }
}

// One CTA per compacted row: softmax over 1024 logits (warp-shuffle reductions,
// 2 block syncs), scale by (1-end_prob), scatter, gather log-prob at Y.
__global__ __launch_bounds__(256) void k_softmax(const int* __restrict__ Y,
                                                 float* __restrict__ out) {
    int cls = blockIdx.y;
    int cnt = g_cnt[cls];
    int r = blockIdx.x;
    if (r >= cnt) return;
    int n = g_rows[cls][r];

    const float4* L = (const float4*)(g_logits + (size_t)n * 1024);
    int tid = threadIdx.x;
    int lane = tid & 31, warp = tid >> 5;
    float4 lv = L[tid];

    __shared__ float wmax[8], wsum[8];

    float m = fmaxf(fmaxf(lv.x, lv.y), fmaxf(lv.z, lv.w));
    #pragma unroll
    for (int o = 16; o; o >>= 1) m = fmaxf(m, __shfl_xor_sync(0xffffffffu, m, o));
    if (lane == 0) wmax[warp] = m;
    __syncthreads();
    float mx = wmax[0];
    #pragma unroll
    for (int i = 1; i < 8; i++) mx = fmaxf(mx, wmax[i]);

    float e0 = expf(lv.x - mx), e1 = expf(lv.y - mx);
    float e2 = expf(lv.z - mx), e3 = expf(lv.w - mx);
    float s = e0 + e1 + e2 + e3;
    #pragma unroll
    for (int o = 16; o; o >>= 1) s += __shfl_xor_sync(0xffffffffu, s, o);
    if (lane == 0) wsum[warp] = s;
    __syncthreads();
    float tot = wsum[0];
    #pragma unroll
    for (int i = 1; i < 8; i++) tot += wsum[i];

    float inv = 1.f / tot;
    float ne = 1.f - g_end_prob[n];
    float sc = inv * ne;

    float p0 = e0 * sc, p1 = e1 * sc, p2 = e2 * sc, p3 = e3 * sc;
    float* dst = out + N_TOK + (size_t)n * CCOLS + (cls ? (2 + FPCNT) : 2);
    int j = tid * 4;
    dst[j + 0] = p0; dst[j + 1] = p1; dst[j + 2] = p2; dst[j + 3] = p3;

    int yv = Y[n];
    int idx = cls ? (yv - 2 - FPCNT) : (yv - 2);
    idx = max(0, min(idx, 1023));
    if (idx >= j && idx < j + 4) {
        float p = (idx == j) ? p0 : (idx == j + 1) ? p1 : (idx == j + 2) ? p2 : p3;
        out[n] = logf(p);
    }
}

extern "C" void kernel_launch(void* const* d_in, const int* in_sizes, int n_in,
                              void* d_out, int out_size) {
    const float* X     = (const float*)d_in[0];
    const int*   pY    = (const int*)d_in[1];
    const int*   Y     = (const int*)d_in[2];
    const float* W_end = (const float*)d_in[3];
    const float* b_end = (const float*)d_in[4];
    const float* W_hcw = (const float*)d_in[5];
    const float* b_hcw = (const float*)d_in[6];
    const float* W_roo = (const float*)d_in[7];
    const float* b_roo = (const float*)d_in[8];
    float* out = (float*)d_out;

    cudaFuncSetAttribute(k_gemm_mma, cudaFuncAttributeMaxDynamicSharedMemorySize, SMEM_SZ);

    k_init<<<1, 1>>>();
    k_classify<<<N_TOK / 8, 256>>>(X, pY, W_end, b_end, out);
    k_wconv<<<(2 * 1024 * HDIM / 4 + 255) / 256, 256>>>(W_hcw, W_roo);
    k_gemm_mma<<<dim3(N_TOK / 128, 1024 / 128, 2), 256, SMEM_SZ>>>(b_hcw, b_roo);
    k_softmax<<<dim3(N_TOK, 2), 256>>>(Y, out);
}

// round 14
// speedup vs baseline: 2.4544x; 1.0286x over previous
#include <cuda_runtime.h>
#include <cuda_bf16.h>
#include <math.h>
#include <cstdint>

// Problem constants
#define N_TOK 16384      // B*S = 32*512
#define HDIM  2048
#define FPCNT 1024
#define SPCNT 1024
#define CCOLS 2050       // 2 + FP + SP

// ---------------- device scratch (allocation-free) ----------------
__device__ float g_end_prob[N_TOK];
__device__ int   g_rows[2][N_TOK];
__device__ int   g_cnt[2];
__device__ float g_logits[(size_t)N_TOK * 1024];
__device__ __align__(16) __nv_bfloat16 g_xhi[(size_t)N_TOK * HDIM];
__device__ __align__(16) __nv_bfloat16 g_xlo[(size_t)N_TOK * HDIM];
__device__ __align__(16) __nv_bfloat16 g_whi[(size_t)2 * 1024 * HDIM];
__device__ __align__(16) __nv_bfloat16 g_wlo[(size_t)2 * 1024 * HDIM];

// ---------------- helpers ----------------
__device__ __forceinline__ uint32_t smem_to_u32(const void* p) {
    uint32_t a;
    asm("{ .reg .u64 t; cvta.to.shared.u64 t, %1; cvt.u32.u64 %0, t; }" : "=r"(a) : "l"(p));
    return a;
}

__device__ __forceinline__ void ldsm4(uint32_t* r, uint32_t addr) {
    asm volatile("ldmatrix.sync.aligned.m8n8.x4.shared.b16 {%0,%1,%2,%3}, [%4];"
                 : "=r"(r[0]), "=r"(r[1]), "=r"(r[2]), "=r"(r[3]) : "r"(addr));
}

__device__ __forceinline__ void mma16816(float* c, const uint32_t* a, const uint32_t* b) {
    asm volatile(
        "mma.sync.aligned.m16n8k16.row.col.f32.bf16.bf16.f32 "
        "{%0,%1,%2,%3}, {%4,%5,%6,%7}, {%8,%9}, {%0,%1,%2,%3};"
        : "+f"(c[0]), "+f"(c[1]), "+f"(c[2]), "+f"(c[3])
        : "r"(a[0]), "r"(a[1]), "r"(a[2]), "r"(a[3]), "r"(b[0]), "r"(b[1]));
}

#define CP_ASYNC16(sa, ga) \
    asm volatile("cp.async.cg.shared.global [%0], [%1], 16;" :: "r"(sa), "l"(ga))
#define CP_COMMIT()  asm volatile("cp.async.commit_group;" ::: "memory")
#define CP_WAIT(n)   asm volatile("cp.async.wait_group %0;" :: "n"(n) : "memory")

// ---------------- kernels ----------------
__global__ void k_init() { g_cnt[0] = 0; g_cnt[1] = 0; }

// One warp per token: end-head GEMV + sigmoid, zero-fill inactive output
// segments, compact rows per class, AND emit bf16 hi/lo split of X.
__global__ void k_classify(const float* __restrict__ X,
                           const int* __restrict__ pY,
                           const float* __restrict__ W_end,
                           const float* __restrict__ b_end,
                           float* __restrict__ out) {
    int warp = threadIdx.x >> 5;
    int lane = threadIdx.x & 31;
    int n = blockIdx.x * 8 + warp;
    if (n >= N_TOK) return;

    const float4* x4 = (const float4*)(X + (size_t)n * HDIM);
    const float4* w4 = (const float4*)W_end;
    __nv_bfloat162* xh = (__nv_bfloat162*)(g_xhi + (size_t)n * HDIM);
    __nv_bfloat162* xl = (__nv_bfloat162*)(g_xlo + (size_t)n * HDIM);

    float s = 0.f;
    #pragma unroll 4
    for (int i = lane; i < HDIM / 4; i += 32) {
        float4 a = x4[i];
        float4 b = w4[i];
        s += a.x * b.x + a.y * b.y + a.z * b.z + a.w * b.w;
        __nv_bfloat16 h0 = __float2bfloat16_rn(a.x), h1 = __float2bfloat16_rn(a.y);
        __nv_bfloat16 h2 = __float2bfloat16_rn(a.z), h3 = __float2bfloat16_rn(a.w);
        __nv_bfloat162 H0; H0.x = h0; H0.y = h1;
        __nv_bfloat162 H1; H1.x = h2; H1.y = h3;
        xh[i * 2 + 0] = H0; xh[i * 2 + 1] = H1;
        __nv_bfloat162 L0, L1;
        L0.x = __float2bfloat16_rn(a.x - __bfloat162float(h0));
        L0.y = __float2bfloat16_rn(a.y - __bfloat162float(h1));
        L1.x = __float2bfloat16_rn(a.z - __bfloat162float(h2));
        L1.y = __float2bfloat16_rn(a.w - __bfloat162float(h3));
        xl[i * 2 + 0] = L0; xl[i * 2 + 1] = L1;
    }
    #pragma unroll
    for (int o = 16; o; o >>= 1) s += __shfl_xor_sync(0xffffffffu, s, o);

    float logit = s + b_end[0];
    float ep = 1.f / (1.f + expf(-logit));

    int cls = pY[n];
    float* orow = out + N_TOK + (size_t)n * CCOLS;

    if (cls == 0) {
        for (int j = lane; j < CCOLS; j += 32)
            orow[j] = (j < 2) ? ep : 0.f;
        if (lane == 0) { g_end_prob[n] = ep; out[n] = logf(ep); }
    } else if (cls == 1) {
        for (int j = lane; j < CCOLS; j += 32)
            if (j < 2 || j >= 2 + FPCNT) orow[j] = 0.f;
        if (lane == 0) {
            g_end_prob[n] = ep;
            int r = atomicAdd(&g_cnt[0], 1);
            g_rows[0][r] = n;
        }
    } else {
        for (int j = lane; j < 2 + FPCNT; j += 32)
            orow[j] = 0.f;
        if (lane == 0) {
            g_end_prob[n] = ep;
            int r = atomicAdd(&g_cnt[1], 1);
            g_rows[1][r] = n;
        }
    }
}

// Split both weight matrices into bf16 hi/lo (hcw -> slot 0, roo -> slot 1).
__global__ void k_wconv(const float* __restrict__ Wh, const float* __restrict__ Wr) {
    size_t i = (size_t)blockIdx.x * blockDim.x + threadIdx.x;   // per float4
    const size_t tot = (size_t)2 * 1024 * HDIM / 4;
    if (i >= tot) return;
    const float4* src = (i < tot / 2) ? (const float4*)Wh : (const float4*)Wr;
    size_t j = (i < tot / 2) ? i : i - tot / 2;
    float4 v = src[j];
    __nv_bfloat16 h0 = __float2bfloat16_rn(v.x), h1 = __float2bfloat16_rn(v.y);
    __nv_bfloat16 h2 = __float2bfloat16_rn(v.z), h3 = __float2bfloat16_rn(v.w);
    __nv_bfloat162 H0; H0.x = h0; H0.y = h1;
    __nv_bfloat162 H1; H1.x = h2; H1.y = h3;
    __nv_bfloat162 L0, L1;
    L0.x = __float2bfloat16_rn(v.x - __bfloat162float(h0));
    L0.y = __float2bfloat16_rn(v.y - __bfloat162float(h1));
    L1.x = __float2bfloat16_rn(v.z - __bfloat162float(h2));
    L1.y = __float2bfloat16_rn(v.w - __bfloat162float(h3));
    ((__nv_bfloat162*)g_whi)[i * 2 + 0] = H0;
    ((__nv_bfloat162*)g_whi)[i * 2 + 1] = H1;
    ((__nv_bfloat162*)g_wlo)[i * 2 + 0] = L0;
    ((__nv_bfloat162*)g_wlo)[i * 2 + 1] = L1;
}

// ---------------- HMMA (mma.sync) GEMM ----------------
// Tile: M=128 gathered rows x N=128 cols, BK=32, THREE-stage cp.async pipeline
// with ONE __syncthreads per K-chunk (CUTLASS multistage ordering: wait ->
// sync -> issue load kc+2 -> compute kc). XOR-swizzled 64B rows (chunk^row&3):
// stage = 32KB, 3 stages + rows = 96.5KB -> 2 CTAs/SM. 8 warps, warp tile
// 32x64, 3 bf16 passes (AhBh + AhBl + AlBh) ~ fp32 accuracy.
#define MATB    8192
#define STAGEB  32768
#define OFF_ROWS 98304
#define SMEM_SZ  98816

__global__ __launch_bounds__(256, 2) void k_gemm_mma(const float* __restrict__ b_hcw,
                                                     const float* __restrict__ b_roo) {
    int cls = blockIdx.z;
    int cnt = g_cnt[cls];
    int m0 = blockIdx.x * 128;
    if (m0 >= cnt) return;
    int n0 = blockIdx.y * 128;

    const __nv_bfloat16* Whi = g_whi + (size_t)cls * 1024 * HDIM;
    const __nv_bfloat16* Wlo = g_wlo + (size_t)cls * 1024 * HDIM;
    const float* bias = cls ? b_roo : b_hcw;

    extern __shared__ char smem[];
    uint32_t sb = smem_to_u32(smem);
    int tid = threadIdx.x;
    int lane = tid & 31, wid = tid >> 5;
    int wm = wid >> 1, wn = wid & 1;          // warp grid 4(m) x 2(n)

    int* s_arow = (int*)(smem + OFF_ROWS);
    if (tid < 128) s_arow[tid] = g_rows[cls][min(m0 + tid, cnt - 1)];
    __syncthreads();

    // Per-thread cp.async descriptors: 8 chunks of 16B per stage.
    // chunk c = tid + i*256: mat = c>>9, row = (c&511)>>2, ch = c&3.
    // SMEM offset swizzled: mat*MATB + row*64 + ((ch ^ (row&3))*16).
    const __nv_bfloat16* gbase[8];
    uint32_t soff[8];
    #pragma unroll
    for (int i = 0; i < 8; i++) {
        int c = tid + i * 256;
        int mat = c >> 9, rc = c & 511, row = rc >> 2, ch = rc & 3;
        const __nv_bfloat16* g;
        if (mat == 0)      g = g_xhi + (size_t)s_arow[row] * HDIM;
        else if (mat == 1) g = g_xlo + (size_t)s_arow[row] * HDIM;
        else if (mat == 2) g = Whi + (size_t)(n0 + row) * HDIM;
        else               g = Wlo + (size_t)(n0 + row) * HDIM;
        gbase[i] = g + ch * 8;
        soff[i] = (uint32_t)(mat * MATB + row * 64 + ((ch ^ (row & 3)) * 16));
    }

    float acc[2][8][4];
    #pragma unroll
    for (int a = 0; a < 2; a++)
        #pragma unroll
        for (int b = 0; b < 8; b++)
            #pragma unroll
            for (int c = 0; c < 4; c++) acc[a][b][c] = 0.f;

    #define LOAD_STAGE(kc, buf) do {                         \
        int _ke = (kc) * 32;                                 \
        uint32_t _stb = sb + (uint32_t)(buf) * STAGEB;       \
        _Pragma("unroll")                                    \
        for (int _i = 0; _i < 8; _i++) {                     \
            const void* _ga = gbase[_i] + _ke;               \
            CP_ASYNC16(_stb + soff[_i], _ga);                \
        }                                                    \
        CP_COMMIT();                                         \
    } while (0)

    LOAD_STAGE(0, 0);
    LOAD_STAGE(1, 1);

    int bld = 2;   // buffer for the look-ahead load (kc+2)
    int bcp = 0;   // buffer being computed (kc)
    #pragma unroll 1
    for (int kc = 0; kc < HDIM / 32; kc++) {
        CP_WAIT(1);          // stage kc resident; kc+1 may still be in flight
        __syncthreads();     // everyone done reading buffer bld (last read kc-1)
        if (kc + 2 < HDIM / 32) LOAD_STAGE(kc + 2, bld);

        uint32_t stb = sb + (uint32_t)bcp * STAGEB;
        #pragma unroll
        for (int kk = 0; kk < 2; kk++) {
            uint32_t cA = kk * 2 + ((lane >> 4) & 1);   // 16B chunk idx 0..3
            uint32_t ah[2][4], al[2][4];
            #pragma unroll
            for (int mt = 0; mt < 2; mt++) {
                uint32_t r = wm * 32 + mt * 16 + (lane & 15);
                uint32_t off = r * 64 + ((cA ^ (r & 3)) * 16);
                ldsm4(ah[mt], stb + off);
                ldsm4(al[mt], stb + MATB + off);
            }
            uint32_t rBb = wn * 64 + (lane & 7) + ((lane >> 4) & 1) * 8;
            uint32_t cB = kk * 2 + ((lane >> 3) & 1);
            #pragma unroll
            for (int pp = 0; pp < 2; pp++) {
                uint32_t bh[2][4], bl[2][4];
                #pragma unroll
                for (int q = 0; q < 2; q++) {
                    uint32_t r = rBb + (pp * 2 + q) * 16;
                    uint32_t off = r * 64 + ((cB ^ (r & 3)) * 16);
                    ldsm4(bh[q], stb + 2 * MATB + off);
                    ldsm4(bl[q], stb + 3 * MATB + off);
                }
                // pass 1: ah x bh  (8 independent MMAs)
                #pragma unroll
                for (int mt = 0; mt < 2; mt++)
                    #pragma unroll
                    for (int q = 0; q < 2; q++) {
                        int p = pp * 2 + q;
                        mma16816(acc[mt][2 * p],     ah[mt], bh[q]);
                        mma16816(acc[mt][2 * p + 1], ah[mt], bh[q] + 2);
                    }
                // pass 2: ah x bl
                #pragma unroll
                for (int mt = 0; mt < 2; mt++)
                    #pragma unroll
                    for (int q = 0; q < 2; q++) {
                        int p = pp * 2 + q;
                        mma16816(acc[mt][2 * p],     ah[mt], bl[q]);
                        mma16816(acc[mt][2 * p + 1], ah[mt], bl[q] + 2);
                    }
                // pass 3: al x bh
                #pragma unroll
                for (int mt = 0; mt < 2; mt++)
                    #pragma unroll
                    for (int q = 0; q < 2; q++) {
                        int p = pp * 2 + q;
                        mma16816(acc[mt][2 * p],     al[mt], bh[q]);
                        mma16816(acc[mt][2 * p + 1], al[mt], bh[q] + 2);
                    }
            }
        }
        // rotate ring: next compute buffer, next load buffer
        bcp = (bcp == 2) ? 0 : bcp + 1;
        bld = (bld == 2) ? 0 : bld + 1;
    }
    CP_WAIT(0);

    // Epilogue: scatter logits + bias
    int gi = lane >> 2, ci = (lane & 3) * 2;
    #pragma unroll
    for (int mt = 0; mt < 2; mt++) {
        int lr = wm * 32 + mt * 16 + gi;
        bool ok0 = (m0 + lr) < cnt;
        bool ok1 = (m0 + lr + 8) < cnt;
        float* d0 = g_logits + (size_t)s_arow[lr] * 1024;
        float* d1 = g_logits + (size_t)s_arow[lr + 8] * 1024;
        #pragma unroll
        for (int nt = 0; nt < 8; nt++) {
            int ncol = n0 + wn * 64 + nt * 8 + ci;
            float bb0 = bias[ncol], bb1 = bias[ncol + 1];
            if (ok0) {
                float2 v; v.x = acc[mt][nt][0] + bb0; v.y = acc[mt][nt][1] + bb1;
                *(float2*)(d0 + ncol) = v;
            }
            if (ok1) {
                float2 v; v.x = acc[mt][nt][2] + bb0; v.y = acc[mt][nt][3] + bb1;
                *(float2*)(d1 + ncol) = v;
            }
        }
    }
}

// One CTA per compacted row: softmax over 1024 logits (warp-shuffle reductions,
// 2 block syncs), scale by (1-end_prob), scatter, gather log-prob at Y.
__global__ __launch_bounds__(256) void k_softmax(const int* __restrict__ Y,
                                                 float* __restrict__ out) {
    int cls = blockIdx.y;
    int cnt = g_cnt[cls];
    int r = blockIdx.x;
    if (r >= cnt) return;
    int n = g_rows[cls][r];

    const float4* L = (const float4*)(g_logits + (size_t)n * 1024);
    int tid = threadIdx.x;
    int lane = tid & 31, warp = tid >> 5;
    float4 lv = L[tid];

    __shared__ float wmax[8], wsum[8];

    float m = fmaxf(fmaxf(lv.x, lv.y), fmaxf(lv.z, lv.w));
    #pragma unroll
    for (int o = 16; o; o >>= 1) m = fmaxf(m, __shfl_xor_sync(0xffffffffu, m, o));
    if (lane == 0) wmax[warp] = m;
    __syncthreads();
    float mx = wmax[0];
    #pragma unroll
    for (int i = 1; i < 8; i++) mx = fmaxf(mx, wmax[i]);

    float e0 = expf(lv.x - mx), e1 = expf(lv.y - mx);
    float e2 = expf(lv.z - mx), e3 = expf(lv.w - mx);
    float s = e0 + e1 + e2 + e3;
    #pragma unroll
    for (int o = 16; o; o >>= 1) s += __shfl_xor_sync(0xffffffffu, s, o);
    if (lane == 0) wsum[warp] = s;
    __syncthreads();
    float tot = wsum[0];
    #pragma unroll
    for (int i = 1; i < 8; i++) tot += wsum[i];

    float inv = 1.f / tot;
    float ne = 1.f - g_end_prob[n];
    float sc = inv * ne;

    float p0 = e0 * sc, p1 = e1 * sc, p2 = e2 * sc, p3 = e3 * sc;
    float* dst = out + N_TOK + (size_t)n * CCOLS + (cls ? (2 + FPCNT) : 2);
    int j = tid * 4;
    dst[j + 0] = p0; dst[j + 1] = p1; dst[j + 2] = p2; dst[j + 3] = p3;

    int yv = Y[n];
    int idx = cls ? (yv - 2 - FPCNT) : (yv - 2);
    idx = max(0, min(idx, 1023));
    if (idx >= j && idx < j + 4) {
        float p = (idx == j) ? p0 : (idx == j + 1) ? p1 : (idx == j + 2) ? p2 : p3;
        out[n] = logf(p);
    }
}

extern "C" void kernel_launch(void* const* d_in, const int* in_sizes, int n_in,
                              void* d_out, int out_size) {
    const float* X     = (const float*)d_in[0];
    const int*   pY    = (const int*)d_in[1];
    const int*   Y     = (const int*)d_in[2];
    const float* W_end = (const float*)d_in[3];
    const float* b_end = (const float*)d_in[4];
    const float* W_hcw = (const float*)d_in[5];
    const float* b_hcw = (const float*)d_in[6];
    const float* W_roo = (const float*)d_in[7];
    const float* b_roo = (const float*)d_in[8];
    float* out = (float*)d_out;

    cudaFuncSetAttribute(k_gemm_mma, cudaFuncAttributeMaxDynamicSharedMemorySize, SMEM_SZ);

    k_init<<<1, 1>>>();
    k_classify<<<N_TOK / 8, 256>>>(X, pY, W_end, b_end, out);
    k_wconv<<<(2 * 1024 * HDIM / 4 + 255) / 256, 256>>>(W_hcw, W_roo);
    k_gemm_mma<<<dim3(N_TOK / 128, 1024 / 128, 2), 256, SMEM_SZ>>>(b_hcw, b_roo);
    k_softmax<<<dim3(N_TOK, 2), 256>>>(Y, out);
}

// round 15
// speedup vs baseline: 2.7997x; 1.1407x over previous
#include <cuda_runtime.h>
#include <cuda_bf16.h>
#include <math.h>
#include <cstdint>

// Problem constants
#define N_TOK 16384      // B*S = 32*512
#define HDIM  2048
#define FPCNT 1024
#define SPCNT 1024
#define CCOLS 2050       // 2 + FP + SP

// ---------------- device scratch (allocation-free) ----------------
__device__ float g_end_prob[N_TOK];
__device__ int   g_rows[2][N_TOK];
__device__ int   g_cnt[2];
__device__ float g_logits[(size_t)N_TOK * 1024];
__device__ __align__(16) __nv_bfloat16 g_xhi[(size_t)N_TOK * HDIM];
__device__ __align__(16) __nv_bfloat16 g_xlo[(size_t)N_TOK * HDIM];
__device__ __align__(16) __nv_bfloat16 g_whi[(size_t)2 * 1024 * HDIM];
__device__ __align__(16) __nv_bfloat16 g_wlo[(size_t)2 * 1024 * HDIM];

// ---------------- helpers ----------------
__device__ __forceinline__ uint32_t smem_to_u32(const void* p) {
    uint32_t a;
    asm("{ .reg .u64 t; cvta.to.shared.u64 t, %1; cvt.u32.u64 %0, t; }" : "=r"(a) : "l"(p));
    return a;
}

__device__ __forceinline__ void ldsm4(uint32_t* r, uint32_t addr) {
    asm volatile("ldmatrix.sync.aligned.m8n8.x4.shared.b16 {%0,%1,%2,%3}, [%4];"
                 : "=r"(r[0]), "=r"(r[1]), "=r"(r[2]), "=r"(r[3]) : "r"(addr));
}

__device__ __forceinline__ void mma16816(float* c, const uint32_t* a, const uint32_t* b) {
    asm volatile(
        "mma.sync.aligned.m16n8k16.row.col.f32.bf16.bf16.f32 "
        "{%0,%1,%2,%3}, {%4,%5,%6,%7}, {%8,%9}, {%0,%1,%2,%3};"
        : "+f"(c[0]), "+f"(c[1]), "+f"(c[2]), "+f"(c[3])
        : "r"(a[0]), "r"(a[1]), "r"(a[2]), "r"(a[3]), "r"(b[0]), "r"(b[1]));
}

#define CP_ASYNC16(sa, ga) \
    asm volatile("cp.async.cg.shared.global [%0], [%1], 16;" :: "r"(sa), "l"(ga))
#define CP_COMMIT()  asm volatile("cp.async.commit_group;" ::: "memory")
#define CP_WAIT(n)   asm volatile("cp.async.wait_group %0;" :: "n"(n) : "memory")

// Conflict-free 64B-row swizzle: chunk ch of row r lives at 16B-slot
// (ch ^ ((r>>1)&3)). Combined with the (r&1)*4 offset implicit in r*64,
// rows 0..7 of an ldmatrix phase hit all 8 distinct 16B slots of the
// 128B line set -> zero bank conflicts (the (r&3) variant collided r, r+4).
__device__ __forceinline__ uint32_t swz_off(uint32_t r, uint32_t ch) {
    return r * 64 + ((ch ^ ((r >> 1) & 3)) * 16);
}

// ---------------- kernels ----------------
__global__ void k_init() { g_cnt[0] = 0; g_cnt[1] = 0; }

// One warp per token: end-head GEMV + sigmoid, zero-fill inactive output
// segments, compact rows per class, AND emit bf16 hi/lo split of X.
__global__ void k_classify(const float* __restrict__ X,
                           const int* __restrict__ pY,
                           const float* __restrict__ W_end,
                           const float* __restrict__ b_end,
                           float* __restrict__ out) {
    int warp = threadIdx.x >> 5;
    int lane = threadIdx.x & 31;
    int n = blockIdx.x * 8 + warp;
    if (n >= N_TOK) return;

    const float4* x4 = (const float4*)(X + (size_t)n * HDIM);
    const float4* w4 = (const float4*)W_end;
    __nv_bfloat162* xh = (__nv_bfloat162*)(g_xhi + (size_t)n * HDIM);
    __nv_bfloat162* xl = (__nv_bfloat162*)(g_xlo + (size_t)n * HDIM);

    float s = 0.f;
    #pragma unroll 4
    for (int i = lane; i < HDIM / 4; i += 32) {
        float4 a = x4[i];
        float4 b = w4[i];
        s += a.x * b.x + a.y * b.y + a.z * b.z + a.w * b.w;
        __nv_bfloat16 h0 = __float2bfloat16_rn(a.x), h1 = __float2bfloat16_rn(a.y);
        __nv_bfloat16 h2 = __float2bfloat16_rn(a.z), h3 = __float2bfloat16_rn(a.w);
        __nv_bfloat162 H0; H0.x = h0; H0.y = h1;
        __nv_bfloat162 H1; H1.x = h2; H1.y = h3;
        xh[i * 2 + 0] = H0; xh[i * 2 + 1] = H1;
        __nv_bfloat162 L0, L1;
        L0.x = __float2bfloat16_rn(a.x - __bfloat162float(h0));
        L0.y = __float2bfloat16_rn(a.y - __bfloat162float(h1));
        L1.x = __float2bfloat16_rn(a.z - __bfloat162float(h2));
        L1.y = __float2bfloat16_rn(a.w - __bfloat162float(h3));
        xl[i * 2 + 0] = L0; xl[i * 2 + 1] = L1;
    }
    #pragma unroll
    for (int o = 16; o; o >>= 1) s += __shfl_xor_sync(0xffffffffu, s, o);

    float logit = s + b_end[0];
    float ep = 1.f / (1.f + expf(-logit));

    int cls = pY[n];
    float* orow = out + N_TOK + (size_t)n * CCOLS;

    if (cls == 0) {
        for (int j = lane; j < CCOLS; j += 32)
            orow[j] = (j < 2) ? ep : 0.f;
        if (lane == 0) { g_end_prob[n] = ep; out[n] = logf(ep); }
    } else if (cls == 1) {
        for (int j = lane; j < CCOLS; j += 32)
            if (j < 2 || j >= 2 + FPCNT) orow[j] = 0.f;
        if (lane == 0) {
            g_end_prob[n] = ep;
            int r = atomicAdd(&g_cnt[0], 1);
            g_rows[0][r] = n;
        }
    } else {
        for (int j = lane; j < 2 + FPCNT; j += 32)
            orow[j] = 0.f;
        if (lane == 0) {
            g_end_prob[n] = ep;
            int r = atomicAdd(&g_cnt[1], 1);
            g_rows[1][r] = n;
        }
    }
}

// Split both weight matrices into bf16 hi/lo (hcw -> slot 0, roo -> slot 1).
__global__ void k_wconv(const float* __restrict__ Wh, const float* __restrict__ Wr) {
    size_t i = (size_t)blockIdx.x * blockDim.x + threadIdx.x;   // per float4
    const size_t tot = (size_t)2 * 1024 * HDIM / 4;
    if (i >= tot) return;
    const float4* src = (i < tot / 2) ? (const float4*)Wh : (const float4*)Wr;
    size_t j = (i < tot / 2) ? i : i - tot / 2;
    float4 v = src[j];
    __nv_bfloat16 h0 = __float2bfloat16_rn(v.x), h1 = __float2bfloat16_rn(v.y);
    __nv_bfloat16 h2 = __float2bfloat16_rn(v.z), h3 = __float2bfloat16_rn(v.w);
    __nv_bfloat162 H0; H0.x = h0; H0.y = h1;
    __nv_bfloat162 H1; H1.x = h2; H1.y = h3;
    __nv_bfloat162 L0, L1;
    L0.x = __float2bfloat16_rn(v.x - __bfloat162float(h0));
    L0.y = __float2bfloat16_rn(v.y - __bfloat162float(h1));
    L1.x = __float2bfloat16_rn(v.z - __bfloat162float(h2));
    L1.y = __float2bfloat16_rn(v.w - __bfloat162float(h3));
    ((__nv_bfloat162*)g_whi)[i * 2 + 0] = H0;
    ((__nv_bfloat162*)g_whi)[i * 2 + 1] = H1;
    ((__nv_bfloat162*)g_wlo)[i * 2 + 0] = L0;
    ((__nv_bfloat162*)g_wlo)[i * 2 + 1] = L1;
}

// ---------------- HMMA (mma.sync) GEMM ----------------
// Tile: M=128 gathered rows x N=128 cols, BK=32, 3-stage cp.async pipeline,
// one __syncthreads per K-chunk. Conflict-free XOR swizzle (see swz_off).
// Stage = 32KB, 3 stages + rows = 96.5KB -> 2 CTAs/SM. 8 warps, warp tile
// 32x64, 3 bf16 passes (AhBh + AhBl + AlBh) ~ fp32 accuracy.
#define MATB    8192
#define STAGEB  32768
#define OFF_ROWS 98304
#define SMEM_SZ  98816

__global__ __launch_bounds__(256, 2) void k_gemm_mma(const float* __restrict__ b_hcw,
                                                     const float* __restrict__ b_roo) {
    int cls = blockIdx.z;
    int cnt = g_cnt[cls];
    int m0 = blockIdx.x * 128;
    if (m0 >= cnt) return;
    int n0 = blockIdx.y * 128;

    const __nv_bfloat16* Whi = g_whi + (size_t)cls * 1024 * HDIM;
    const __nv_bfloat16* Wlo = g_wlo + (size_t)cls * 1024 * HDIM;
    const float* bias = cls ? b_roo : b_hcw;

    extern __shared__ char smem[];
    uint32_t sb = smem_to_u32(smem);
    int tid = threadIdx.x;
    int lane = tid & 31, wid = tid >> 5;
    int wm = wid >> 1, wn = wid & 1;          // warp grid 4(m) x 2(n)

    int* s_arow = (int*)(smem + OFF_ROWS);
    if (tid < 128) s_arow[tid] = g_rows[cls][min(m0 + tid, cnt - 1)];
    __syncthreads();

    // Per-thread cp.async descriptors: 8 chunks of 16B per stage.
    // chunk c = tid + i*256: mat = c>>9, row = (c&511)>>2, ch = c&3.
    const __nv_bfloat16* gbase[8];
    uint32_t soff[8];
    #pragma unroll
    for (int i = 0; i < 8; i++) {
        int c = tid + i * 256;
        int mat = c >> 9, rc = c & 511, row = rc >> 2, ch = rc & 3;
        const __nv_bfloat16* g;
        if (mat == 0)      g = g_xhi + (size_t)s_arow[row] * HDIM;
        else if (mat == 1) g = g_xlo + (size_t)s_arow[row] * HDIM;
        else if (mat == 2) g = Whi + (size_t)(n0 + row) * HDIM;
        else               g = Wlo + (size_t)(n0 + row) * HDIM;
        gbase[i] = g + ch * 8;
        soff[i] = (uint32_t)(mat * MATB) + swz_off((uint32_t)row, (uint32_t)ch);
    }

    float acc[2][8][4];
    #pragma unroll
    for (int a = 0; a < 2; a++)
        #pragma unroll
        for (int b = 0; b < 8; b++)
            #pragma unroll
            for (int c = 0; c < 4; c++) acc[a][b][c] = 0.f;

    #define LOAD_STAGE(kc, buf) do {                         \
        int _ke = (kc) * 32;                                 \
        uint32_t _stb = sb + (uint32_t)(buf) * STAGEB;       \
        _Pragma("unroll")                                    \
        for (int _i = 0; _i < 8; _i++) {                     \
            const void* _ga = gbase[_i] + _ke;               \
            CP_ASYNC16(_stb + soff[_i], _ga);                \
        }                                                    \
        CP_COMMIT();                                         \
    } while (0)

    LOAD_STAGE(0, 0);
    LOAD_STAGE(1, 1);

    int bld = 2;   // buffer for the look-ahead load (kc+2)
    int bcp = 0;   // buffer being computed (kc)
    #pragma unroll 1
    for (int kc = 0; kc < HDIM / 32; kc++) {
        CP_WAIT(1);          // stage kc resident; kc+1 may still be in flight
        __syncthreads();     // everyone done reading buffer bld (last read kc-1)
        if (kc + 2 < HDIM / 32) LOAD_STAGE(kc + 2, bld);

        uint32_t stb = sb + (uint32_t)bcp * STAGEB;
        #pragma unroll
        for (int kk = 0; kk < 2; kk++) {
            uint32_t cA = kk * 2 + ((lane >> 4) & 1);   // 16B chunk idx 0..3
            uint32_t ah[2][4], al[2][4];
            #pragma unroll
            for (int mt = 0; mt < 2; mt++) {
                uint32_t r = wm * 32 + mt * 16 + (lane & 15);
                uint32_t off = swz_off(r, cA);
                ldsm4(ah[mt], stb + off);
                ldsm4(al[mt], stb + MATB + off);
            }
            uint32_t rBb = wn * 64 + (lane & 7) + ((lane >> 4) & 1) * 8;
            uint32_t cB = kk * 2 + ((lane >> 3) & 1);
            #pragma unroll
            for (int pp = 0; pp < 2; pp++) {
                uint32_t bh[2][4], bl[2][4];
                #pragma unroll
                for (int q = 0; q < 2; q++) {
                    uint32_t r = rBb + (pp * 2 + q) * 16;
                    uint32_t off = swz_off(r, cB);
                    ldsm4(bh[q], stb + 2 * MATB + off);
                    ldsm4(bl[q], stb + 3 * MATB + off);
                }
                // pass 1: ah x bh  (8 independent MMAs)
                #pragma unroll
                for (int mt = 0; mt < 2; mt++)
                    #pragma unroll
                    for (int q = 0; q < 2; q++) {
                        int p = pp * 2 + q;
                        mma16816(acc[mt][2 * p],     ah[mt], bh[q]);
                        mma16816(acc[mt][2 * p + 1], ah[mt], bh[q] + 2);
                    }
                // pass 2: ah x bl
                #pragma unroll
                for (int mt = 0; mt < 2; mt++)
                    #pragma unroll
                    for (int q = 0; q < 2; q++) {
                        int p = pp * 2 + q;
                        mma16816(acc[mt][2 * p],     ah[mt], bl[q]);
                        mma16816(acc[mt][2 * p + 1], ah[mt], bl[q] + 2);
                    }
                // pass 3: al x bh
                #pragma unroll
                for (int mt = 0; mt < 2; mt++)
                    #pragma unroll
                    for (int q = 0; q < 2; q++) {
                        int p = pp * 2 + q;
                        mma16816(acc[mt][2 * p],     al[mt], bh[q]);
                        mma16816(acc[mt][2 * p + 1], al[mt], bh[q] + 2);
                    }
            }
        }
        // rotate ring: next compute buffer, next load buffer
        bcp = (bcp == 2) ? 0 : bcp + 1;
        bld = (bld == 2) ? 0 : bld + 1;
    }
    CP_WAIT(0);

    // Epilogue: scatter logits + bias
    int gi = lane >> 2, ci = (lane & 3) * 2;
    #pragma unroll
    for (int mt = 0; mt < 2; mt++) {
        int lr = wm * 32 + mt * 16 + gi;
        bool ok0 = (m0 + lr) < cnt;
        bool ok1 = (m0 + lr + 8) < cnt;
        float* d0 = g_logits + (size_t)s_arow[lr] * 1024;
        float* d1 = g_logits + (size_t)s_arow[lr + 8] * 1024;
        #pragma unroll
        for (int nt = 0; nt < 8; nt++) {
            int ncol = n0 + wn * 64 + nt * 8 + ci;
            float bb0 = bias[ncol], bb1 = bias[ncol + 1];
            if (ok0) {
                float2 v; v.x = acc[mt][nt][0] + bb0; v.y = acc[mt][nt][1] + bb1;
                *(float2*)(d0 + ncol) = v;
            }
            if (ok1) {
                float2 v; v.x = acc[mt][nt][2] + bb0; v.y = acc[mt][nt][3] + bb1;
                *(float2*)(d1 + ncol) = v;
            }
        }
    }
}

// One CTA per compacted row: softmax over 1024 logits (warp-shuffle reductions,
// 2 block syncs), scale by (1-end_prob), scatter, gather log-prob at Y.
__global__ __launch_bounds__(256) void k_softmax(const int* __restrict__ Y,
                                                 float* __restrict__ out) {
    int cls = blockIdx.y;
    int cnt = g_cnt[cls];
    int r = blockIdx.x;
    if (r >= cnt) return;
    int n = g_rows[cls][r];

    const float4* L = (const float4*)(g_logits + (size_t)n * 1024);
    int tid = threadIdx.x;
    int lane = tid & 31, warp = tid >> 5;
    float4 lv = L[tid];

    __shared__ float wmax[8], wsum[8];

    float m = fmaxf(fmaxf(lv.x, lv.y), fmaxf(lv.z, lv.w));
    #pragma unroll
    for (int o = 16; o; o >>= 1) m = fmaxf(m, __shfl_xor_sync(0xffffffffu, m, o));
    if (lane == 0) wmax[warp] = m;
    __syncthreads();
    float mx = wmax[0];
    #pragma unroll
    for (int i = 1; i < 8; i++) mx = fmaxf(mx, wmax[i]);

    float e0 = expf(lv.x - mx), e1 = expf(lv.y - mx);
    float e2 = expf(lv.z - mx), e3 = expf(lv.w - mx);
    float s = e0 + e1 + e2 + e3;
    #pragma unroll
    for (int o = 16; o; o >>= 1) s += __shfl_xor_sync(0xffffffffu, s, o);
    if (lane == 0) wsum[warp] = s;
    __syncthreads();
    float tot = wsum[0];
    #pragma unroll
    for (int i = 1; i < 8; i++) tot += wsum[i];

    float inv = 1.f / tot;
    float ne = 1.f - g_end_prob[n];
    float sc = inv * ne;

    float p0 = e0 * sc, p1 = e1 * sc, p2 = e2 * sc, p3 = e3 * sc;
    float* dst = out + N_TOK + (size_t)n * CCOLS + (cls ? (2 + FPCNT) : 2);
    int j = tid * 4;
    dst[j + 0] = p0; dst[j + 1] = p1; dst[j + 2] = p2; dst[j + 3] = p3;

    int yv = Y[n];
    int idx = cls ? (yv - 2 - FPCNT) : (yv - 2);
    idx = max(0, min(idx, 1023));
    if (idx >= j && idx < j + 4) {
        float p = (idx == j) ? p0 : (idx == j + 1) ? p1 : (idx == j + 2) ? p2 : p3;
        out[n] = logf(p);
    }
}

extern "C" void kernel_launch(void* const* d_in, const int* in_sizes, int n_in,
                              void* d_out, int out_size) {
    const float* X     = (const float*)d_in[0];
    const int*   pY    = (const int*)d_in[1];
    const int*   Y     = (const int*)d_in[2];
    const float* W_end = (const float*)d_in[3];
    const float* b_end = (const float*)d_in[4];
    const float* W_hcw = (const float*)d_in[5];
    const float* b_hcw = (const float*)d_in[6];
    const float* W_roo = (const float*)d_in[7];
    const float* b_roo = (const float*)d_in[8];
    float* out = (float*)d_out;

    cudaFuncSetAttribute(k_gemm_mma, cudaFuncAttributeMaxDynamicSharedMemorySize, SMEM_SZ);

    k_init<<<1, 1>>>();
    k_classify<<<N_TOK / 8, 256>>>(X, pY, W_end, b_end, out);
    k_wconv<<<(2 * 1024 * HDIM / 4 + 255) / 256, 256>>>(W_hcw, W_roo);
    k_gemm_mma<<<dim3(N_TOK / 128, 1024 / 128, 2), 256, SMEM_SZ>>>(b_hcw, b_roo);
    k_softmax<<<dim3(N_TOK, 2), 256>>>(Y, out);
}

// round 17
// speedup vs baseline: 2.8024x; 1.0010x over previous
#include <cuda_runtime.h>
#include <cuda_bf16.h>
#include <math.h>
#include <cstdint>

// Problem constants
#define N_TOK 16384      // B*S = 32*512
#define HDIM  2048
#define FPCNT 1024
#define SPCNT 1024
#define CCOLS 2050       // 2 + FP + SP

// ---------------- device scratch (allocation-free) ----------------
__device__ float g_end_prob[N_TOK];
__device__ int   g_rows[2][N_TOK];
__device__ int   g_cnt[2];
__device__ int   g_ticket;
__device__ float g_logits[(size_t)N_TOK * 1024];
__device__ __align__(16) __nv_bfloat16 g_xhi[(size_t)N_TOK * HDIM];
__device__ __align__(16) __nv_bfloat16 g_xlo[(size_t)N_TOK * HDIM];
__device__ __align__(16) __nv_bfloat16 g_whi[(size_t)2 * 1024 * HDIM];
__device__ __align__(16) __nv_bfloat16 g_wlo[(size_t)2 * 1024 * HDIM];

// ---------------- helpers ----------------
__device__ __forceinline__ uint32_t smem_to_u32(const void* p) {
    uint32_t a;
    asm("{ .reg .u64 t; cvta.to.shared.u64 t, %1; cvt.u32.u64 %0, t; }" : "=r"(a) : "l"(p));
    return a;
}

__device__ __forceinline__ void ldsm4(uint32_t* r, uint32_t addr) {
    asm volatile("ldmatrix.sync.aligned.m8n8.x4.shared.b16 {%0,%1,%2,%3}, [%4];"
                 : "=r"(r[0]), "=r"(r[1]), "=r"(r[2]), "=r"(r[3]) : "r"(addr));
}

__device__ __forceinline__ void mma16816(float* c, const uint32_t* a, const uint32_t* b) {
    asm volatile(
        "mma.sync.aligned.m16n8k16.row.col.f32.bf16.bf16.f32 "
        "{%0,%1,%2,%3}, {%4,%5,%6,%7}, {%8,%9}, {%0,%1,%2,%3};"
        : "+f"(c[0]), "+f"(c[1]), "+f"(c[2]), "+f"(c[3])
        : "r"(a[0]), "r"(a[1]), "r"(a[2]), "r"(a[3]), "r"(b[0]), "r"(b[1]));
}

#define CP_ASYNC16(sa, ga) \
    asm volatile("cp.async.cg.shared.global [%0], [%1], 16;" :: "r"(sa), "l"(ga))
#define CP_COMMIT()  asm volatile("cp.async.commit_group;" ::: "memory")
#define CP_WAIT(n)   asm volatile("cp.async.wait_group %0;" :: "n"(n) : "memory")

// Conflict-free 64B-row swizzle: chunk ch of row r lives at 16B-slot
// (ch ^ ((r>>1)&3)); rows 0..7 of an ldmatrix phase hit all 8 distinct slots.
__device__ __forceinline__ uint32_t swz_off(uint32_t r, uint32_t ch) {
    return r * 64 + ((ch ^ ((r >> 1) & 3)) * 16);
}

// ---------------- kernels ----------------
__global__ void k_init() { g_cnt[0] = 0; g_cnt[1] = 0; g_ticket = 0; }

// Merged prep kernel: blocks [0,2048) do classify (one warp per token:
// end-head GEMV + sigmoid, zero-fill inactive output segments, compact rows,
// emit bf16 hi/lo split of X); blocks [2048,6144) do the W hi/lo split.
__global__ void k_prep(const float* __restrict__ X,
                       const int* __restrict__ pY,
                       const float* __restrict__ W_end,
                       const float* __restrict__ b_end,
                       const float* __restrict__ Wh,
                       const float* __restrict__ Wr,
                       float* __restrict__ out) {
    if (blockIdx.x >= 2048) {
        // ---- weight split: per float4 ----
        size_t i = (size_t)(blockIdx.x - 2048) * blockDim.x + threadIdx.x;
        const size_t tot = (size_t)2 * 1024 * HDIM / 4;
        if (i >= tot) return;
        const float4* src = (i < tot / 2) ? (const float4*)Wh : (const float4*)Wr;
        size_t j = (i < tot / 2) ? i : i - tot / 2;
        float4 v = src[j];
        __nv_bfloat16 h0 = __float2bfloat16_rn(v.x), h1 = __float2bfloat16_rn(v.y);
        __nv_bfloat16 h2 = __float2bfloat16_rn(v.z), h3 = __float2bfloat16_rn(v.w);
        __nv_bfloat162 H0; H0.x = h0; H0.y = h1;
        __nv_bfloat162 H1; H1.x = h2; H1.y = h3;
        __nv_bfloat162 L0, L1;
        L0.x = __float2bfloat16_rn(v.x - __bfloat162float(h0));
        L0.y = __float2bfloat16_rn(v.y - __bfloat162float(h1));
        L1.x = __float2bfloat16_rn(v.z - __bfloat162float(h2));
        L1.y = __float2bfloat16_rn(v.w - __bfloat162float(h3));
        ((__nv_bfloat162*)g_whi)[i * 2 + 0] = H0;
        ((__nv_bfloat162*)g_whi)[i * 2 + 1] = H1;
        ((__nv_bfloat162*)g_wlo)[i * 2 + 0] = L0;
        ((__nv_bfloat162*)g_wlo)[i * 2 + 1] = L1;
        return;
    }

    // ---- classify ----
    int warp = threadIdx.x >> 5;
    int lane = threadIdx.x & 31;
    int n = blockIdx.x * 8 + warp;
    if (n >= N_TOK) return;

    const float4* x4 = (const float4*)(X + (size_t)n * HDIM);
    const float4* w4 = (const float4*)W_end;
    __nv_bfloat162* xh = (__nv_bfloat162*)(g_xhi + (size_t)n * HDIM);
    __nv_bfloat162* xl = (__nv_bfloat162*)(g_xlo + (size_t)n * HDIM);

    float s = 0.f;
    #pragma unroll 4
    for (int i = lane; i < HDIM / 4; i += 32) {
        float4 a = x4[i];
        float4 b = w4[i];
        s += a.x * b.x + a.y * b.y + a.z * b.z + a.w * b.w;
        __nv_bfloat16 h0 = __float2bfloat16_rn(a.x), h1 = __float2bfloat16_rn(a.y);
        __nv_bfloat16 h2 = __float2bfloat16_rn(a.z), h3 = __float2bfloat16_rn(a.w);
        __nv_bfloat162 H0; H0.x = h0; H0.y = h1;
        __nv_bfloat162 H1; H1.x = h2; H1.y = h3;
        xh[i * 2 + 0] = H0; xh[i * 2 + 1] = H1;
        __nv_bfloat162 L0, L1;
        L0.x = __float2bfloat16_rn(a.x - __bfloat162float(h0));
        L0.y = __float2bfloat16_rn(a.y - __bfloat162float(h1));
        L1.x = __float2bfloat16_rn(a.z - __bfloat162float(h2));
        L1.y = __float2bfloat16_rn(a.w - __bfloat162float(h3));
        xl[i * 2 + 0] = L0; xl[i * 2 + 1] = L1;
    }
    #pragma unroll
    for (int o = 16; o; o >>= 1) s += __shfl_xor_sync(0xffffffffu, s, o);

    float logit = s + b_end[0];
    float ep = 1.f / (1.f + expf(-logit));

    int cls = pY[n];
    float* orow = out + N_TOK + (size_t)n * CCOLS;

    if (cls == 0) {
        for (int j = lane; j < CCOLS; j += 32)
            orow[j] = (j < 2) ? ep : 0.f;
        if (lane == 0) { g_end_prob[n] = ep; out[n] = logf(ep); }
    } else if (cls == 1) {
        for (int j = lane; j < CCOLS; j += 32)
            if (j < 2 || j >= 2 + FPCNT) orow[j] = 0.f;
        if (lane == 0) {
            g_end_prob[n] = ep;
            int r = atomicAdd(&g_cnt[0], 1);
            g_rows[0][r] = n;
        }
    } else {
        for (int j = lane; j < 2 + FPCNT; j += 32)
            orow[j] = 0.f;
        if (lane == 0) {
            g_end_prob[n] = ep;
            int r = atomicAdd(&g_cnt[1], 1);
            g_rows[1][r] = n;
        }
    }
}

// ---------------- HMMA (mma.sync) GEMM, persistent ----------------
// Fixed grid of 304 CTAs (2/SM), atomic-ticket work stealing over flattened
// (class, m-tile, n-tile) space -> packs ~688 tiles without wave quantization.
// Per tile: M=128 gathered rows x N=128 cols, BK=32, 3-stage cp.async
// pipeline, one __syncthreads per K-chunk, conflict-free XOR swizzle,
// 8 warps (warp tile 32x64), 3 bf16 passes (AhBh + AhBl + AlBh).
#define MATB    8192
#define STAGEB  32768
#define OFF_ROWS 98304
#define SMEM_SZ  98824
#define GEMM_GRID 304

__global__ __launch_bounds__(256, 2) void k_gemm_mma(const float* __restrict__ b_hcw,
                                                     const float* __restrict__ b_roo) {
    extern __shared__ char smem[];
    uint32_t sb = smem_to_u32(smem);
    int tid = threadIdx.x;
    int lane = tid & 31, wid = tid >> 5;
    int wm = wid >> 1, wn = wid & 1;          // warp grid 4(m) x 2(n)

    int* s_arow = (int*)(smem + OFF_ROWS);
    int* s_tick = (int*)(smem + OFF_ROWS + 512);

    int cnt0 = g_cnt[0], cnt1 = g_cnt[1];
    int nt0 = (cnt0 + 127) >> 7, nt1 = (cnt1 + 127) >> 7;
    int total = (nt0 + nt1) * 8;

    for (;;) {
        __syncthreads();                       // smem (s_arow/s_tick) reusable
        if (tid == 0) *s_tick = atomicAdd(&g_ticket, 1);
        __syncthreads();
        int t = *s_tick;
        if (t >= total) return;

        int cls, mi, n0;
        if (t < nt0 * 8) { cls = 0; mi = t >> 3; n0 = (t & 7) << 7; }
        else { int u = t - nt0 * 8; cls = 1; mi = u >> 3; n0 = (u & 7) << 7; }
        int cnt = cls ? cnt1 : cnt0;
        int m0 = mi << 7;

        const __nv_bfloat16* Whi = g_whi + (size_t)cls * 1024 * HDIM;
        const __nv_bfloat16* Wlo = g_wlo + (size_t)cls * 1024 * HDIM;
        const float* bias = cls ? b_roo : b_hcw;

        if (tid < 128) s_arow[tid] = g_rows[cls][min(m0 + tid, cnt - 1)];
        __syncthreads();

        // Per-thread cp.async descriptors: 8 chunks of 16B per stage.
        const __nv_bfloat16* gbase[8];
        uint32_t soff[8];
        #pragma unroll
        for (int i = 0; i < 8; i++) {
            int c = tid + i * 256;
            int mat = c >> 9, rc = c & 511, row = rc >> 2, ch = rc & 3;
            const __nv_bfloat16* g;
            if (mat == 0)      g = g_xhi + (size_t)s_arow[row] * HDIM;
            else if (mat == 1) g = g_xlo + (size_t)s_arow[row] * HDIM;
            else if (mat == 2) g = Whi + (size_t)(n0 + row) * HDIM;
            else               g = Wlo + (size_t)(n0 + row) * HDIM;
            gbase[i] = g + ch * 8;
            soff[i] = (uint32_t)(mat * MATB) + swz_off((uint32_t)row, (uint32_t)ch);
        }

        float acc[2][8][4];
        #pragma unroll
        for (int a = 0; a < 2; a++)
            #pragma unroll
            for (int b = 0; b < 8; b++)
                #pragma unroll
                for (int c = 0; c < 4; c++) acc[a][b][c] = 0.f;

        #define LOAD_STAGE(kc, buf) do {                         \
            int _ke = (kc) * 32;                                 \
            uint32_t _stb = sb + (uint32_t)(buf) * STAGEB;       \
            _Pragma("unroll")                                    \
            for (int _i = 0; _i < 8; _i++) {                     \
                const void* _ga = gbase[_i] + _ke;               \
                CP_ASYNC16(_stb + soff[_i], _ga);                \
            }                                                    \
            CP_COMMIT();                                         \
        } while (0)

        LOAD_STAGE(0, 0);
        LOAD_STAGE(1, 1);

        int bld = 2;   // buffer for the look-ahead load (kc+2)
        int bcp = 0;   // buffer being computed (kc)
        #pragma unroll 1
        for (int kc = 0; kc < HDIM / 32; kc++) {
            CP_WAIT(1);
            __syncthreads();
            if (kc + 2 < HDIM / 32) LOAD_STAGE(kc + 2, bld);

            uint32_t stb = sb + (uint32_t)bcp * STAGEB;
            #pragma unroll
            for (int kk = 0; kk < 2; kk++) {
                uint32_t cA = kk * 2 + ((lane >> 4) & 1);
                uint32_t ah[2][4], al[2][4];
                #pragma unroll
                for (int mt = 0; mt < 2; mt++) {
                    uint32_t r = wm * 32 + mt * 16 + (lane & 15);
                    uint32_t off = swz_off(r, cA);
                    ldsm4(ah[mt], stb + off);
                    ldsm4(al[mt], stb + MATB + off);
                }
                uint32_t rBb = wn * 64 + (lane & 7) + ((lane >> 4) & 1) * 8;
                uint32_t cB = kk * 2 + ((lane >> 3) & 1);
                #pragma unroll
                for (int pp = 0; pp < 2; pp++) {
                    uint32_t bh[2][4], bl[2][4];
                    #pragma unroll
                    for (int q = 0; q < 2; q++) {
                        uint32_t r = rBb + (pp * 2 + q) * 16;
                        uint32_t off = swz_off(r, cB);
                        ldsm4(bh[q], stb + 2 * MATB + off);
                        ldsm4(bl[q], stb + 3 * MATB + off);
                    }
                    // pass 1: ah x bh  (8 independent MMAs)
                    #pragma unroll
                    for (int mt = 0; mt < 2; mt++)
                        #pragma unroll
                        for (int q = 0; q < 2; q++) {
                            int p = pp * 2 + q;
                            mma16816(acc[mt][2 * p],     ah[mt], bh[q]);
                            mma16816(acc[mt][2 * p + 1], ah[mt], bh[q] + 2);
                        }
                    // pass 2: ah x bl
                    #pragma unroll
                    for (int mt = 0; mt < 2; mt++)
                        #pragma unroll
                        for (int q = 0; q < 2; q++) {
                            int p = pp * 2 + q;
                            mma16816(acc[mt][2 * p],     ah[mt], bl[q]);
                            mma16816(acc[mt][2 * p + 1], ah[mt], bl[q] + 2);
                        }
                    // pass 3: al x bh
                    #pragma unroll
                    for (int mt = 0; mt < 2; mt++)
                        #pragma unroll
                        for (int q = 0; q < 2; q++) {
                            int p = pp * 2 + q;
                            mma16816(acc[mt][2 * p],     al[mt], bh[q]);
                            mma16816(acc[mt][2 * p + 1], al[mt], bh[q] + 2);
                        }
                }
            }
            bcp = (bcp == 2) ? 0 : bcp + 1;
            bld = (bld == 2) ? 0 : bld + 1;
        }
        CP_WAIT(0);

        // Epilogue: scatter logits + bias
        int gi = lane >> 2, ci = (lane & 3) * 2;
        #pragma unroll
        for (int mt = 0; mt < 2; mt++) {
            int lr = wm * 32 + mt * 16 + gi;
            bool ok0 = (m0 + lr) < cnt;
            bool ok1 = (m0 + lr + 8) < cnt;
            float* d0 = g_logits + (size_t)s_arow[lr] * 1024;
            float* d1 = g_logits + (size_t)s_arow[lr + 8] * 1024;
            #pragma unroll
            for (int nt = 0; nt < 8; nt++) {
                int ncol = n0 + wn * 64 + nt * 8 + ci;
                float bb0 = bias[ncol], bb1 = bias[ncol + 1];
                if (ok0) {
                    float2 v; v.x = acc[mt][nt][0] + bb0; v.y = acc[mt][nt][1] + bb1;
                    *(float2*)(d0 + ncol) = v;
                }
                if (ok1) {
                    float2 v; v.x = acc[mt][nt][2] + bb0; v.y = acc[mt][nt][3] + bb1;
                    *(float2*)(d1 + ncol) = v;
                }
            }
        }
    }
}

// One CTA per compacted row: softmax over 1024 logits (warp-shuffle reductions,
// 2 block syncs), scale by (1-end_prob), scatter, gather log-prob at Y.
__global__ __launch_bounds__(256) void k_softmax(const int* __restrict__ Y,
                                                 float* __restrict__ out) {
    int cls = blockIdx.y;
    int cnt = g_cnt[cls];
    int r = blockIdx.x;
    if (r >= cnt) return;
    int n = g_rows[cls][r];

    const float4* L = (const float4*)(g_logits + (size_t)n * 1024);
    int tid = threadIdx.x;
    int lane = tid & 31, warp = tid >> 5;
    float4 lv = L[tid];

    __shared__ float wmax[8], wsum[8];

    float m = fmaxf(fmaxf(lv.x, lv.y), fmaxf(lv.z, lv.w));
    #pragma unroll
    for (int o = 16; o; o >>= 1) m = fmaxf(m, __shfl_xor_sync(0xffffffffu, m, o));
    if (lane == 0) wmax[warp] = m;
    __syncthreads();
    float mx = wmax[0];
    #pragma unroll
    for (int i = 1; i < 8; i++) mx = fmaxf(mx, wmax[i]);

    float e0 = expf(lv.x - mx), e1 = expf(lv.y - mx);
    float e2 = expf(lv.z - mx), e3 = expf(lv.w - mx);
    float s = e0 + e1 + e2 + e3;
    #pragma unroll
    for (int o = 16; o; o >>= 1) s += __shfl_xor_sync(0xffffffffu, s, o);
    if (lane == 0) wsum[warp] = s;
    __syncthreads();
    float tot = wsum[0];
    #pragma unroll
    for (int i = 1; i < 8; i++) tot += wsum[i];

    float inv = 1.f / tot;
    float ne = 1.f - g_end_prob[n];
    float sc = inv * ne;

    float p0 = e0 * sc, p1 = e1 * sc, p2 = e2 * sc, p3 = e3 * sc;
    float* dst = out + N_TOK + (size_t)n * CCOLS + (cls ? (2 + FPCNT) : 2);
    int j = tid * 4;
    dst[j + 0] = p0; dst[j + 1] = p1; dst[j + 2] = p2; dst[j + 3] = p3;

    int yv = Y[n];
    int idx = cls ? (yv - 2 - FPCNT) : (yv - 2);
    idx = max(0, min(idx, 1023));
    if (idx >= j && idx < j + 4) {
        float p = (idx == j) ? p0 : (idx == j + 1) ? p1 : (idx == j + 2) ? p2 : p3;
        out[n] = logf(p);
    }
}

extern "C" void kernel_launch(void* const* d_in, const int* in_sizes, int n_in,
                              void* d_out, int out_size) {
    const float* X     = (const float*)d_in[0];
    const int*   pY    = (const int*)d_in[1];
    const int*   Y     = (const int*)d_in[2];
    const float* W_end = (const float*)d_in[3];
    const float* b_end = (const float*)d_in[4];
    const float* W_hcw = (const float*)d_in[5];
    const float* b_hcw = (const float*)d_in[6];
    const float* W_roo = (const float*)d_in[7];
    const float* b_roo = (const float*)d_in[8];
    float* out = (float*)d_out;

    cudaFuncSetAttribute(k_gemm_mma, cudaFuncAttributeMaxDynamicSharedMemorySize, SMEM_SZ);

    k_init<<<1, 1>>>();
    k_prep<<<2048 + 4096, 256>>>(X, pY, W_end, b_end, W_hcw, W_roo, out);
    k_gemm_mma<<<GEMM_GRID, 256, SMEM_SZ>>>(b_hcw, b_roo);
    k_softmax<<<dim3(N_TOK, 2), 256>>>(Y, out);
}